// round 10
// baseline (speedup 1.0000x reference)
#include <cuda_runtime.h>
#include <cuda_fp16.h>
#include <stdint.h>
#include <math.h>

// dims: b=4, n=4096, d=128, hid=512, CHUNK=64
#define NTOK 16384
#define D 128
#define HID 512
#define NC 64
#define BATCH 4
#define SLICES 8
#define NTHR 512

// ---------------- scratch ----------------
__device__ float  g_K [NTOK*D];
__device__ float  g_V [NTOK*D];
__device__ float  g_Q [NTOK*D];
__device__ float  g_GP[NTOK*HID];
__device__ __half g_seqH[NTOK*D];
__device__ __half g_wkH[D*D], g_wvH[D*D], g_wqH[D*D];
__device__ __half g_w1H[D*HID];
__device__ __half g_w2H[HID*D];
__device__ __half g_KH [NTOK*D];
__device__ __half g_QH [NTOK*D];
__device__ __half g_AH [NTOK*HID];
__device__ __half g_dHH[NTOK*D];
__device__ __half g_dZH[NTOK*HID];
__device__ __half g_A2H[NTOK*HID];
__device__ __half g_w1fH[BATCH*D*HID];
__device__ __half g_w2fH[BATCH*HID*D];
__device__ float  g_lrv [BATCH*NC];
__device__ float  g_keep[BATCH*NC];
__device__ float  g_eta [BATCH*NC];
__device__ float  g_coef[BATCH*NC];
__device__ float  g_gfp[256*D];
__device__ float  g_gf [BATCH*D];
__device__ float  g_w1p[BATCH*SLICES*D*HID];
__device__ float  g_w2p[BATCH*SLICES*HID*D];

// ---------------- helpers ----------------
__device__ __forceinline__ float sigm(float x){ return 1.f/(1.f+expf(-x)); }
__device__ __forceinline__ float tanh_fast(float u){
    float e = __expf(2.f*u);
    return 1.f - __fdividef(2.f, e + 1.f);
}
__device__ __forceinline__ void gelu_both(float x, float& a, float& gp){
    const float c0 = 0.7978845608028654f, c1 = 0.044715f;
    float x2 = x*x;
    float t = tanh_fast(c0*x*(1.f + c1*x2));
    a  = 0.5f*x*(1.f + t);
    gp = 0.5f*(1.f + t) + 0.5f*x*(1.f - t*t)*c0*(1.f + 3.f*c1*x2);
}
__device__ __forceinline__ float gelu_f(float x){
    float t = tanh_fast(0.7978845608028654f*x*(1.f + 0.044715f*x*x));
    return 0.5f*x*(1.f + t);
}
__device__ __forceinline__ uint32_t h2pack(float lo, float hi){
    __half2 h = __floats2half2_rn(lo, hi);
    return *reinterpret_cast<uint32_t*>(&h);
}
__device__ __forceinline__ void mma16(float& c0, float& c1, float& c2, float& c3,
                                      uint32_t a0, uint32_t a1, uint32_t a2, uint32_t a3,
                                      uint32_t b0, uint32_t b1){
    asm volatile("mma.sync.aligned.m16n8k16.row.col.f32.f16.f16.f32 "
                 "{%0,%1,%2,%3}, {%4,%5,%6,%7}, {%8,%9}, {%0,%1,%2,%3};"
                 : "+f"(c0), "+f"(c1), "+f"(c2), "+f"(c3)
                 : "r"(a0), "r"(a1), "r"(a2), "r"(a3), "r"(b0), "r"(b1));
}
__device__ __forceinline__ uint32_t smem_u32(const void* p){
    uint32_t a;
    asm("{ .reg .u64 t; cvta.to.shared.u64 t, %1; cvt.u32.u64 %0, t; }" : "=r"(a) : "l"(p));
    return a;
}
__device__ __forceinline__ void cp16(uint32_t dst, const void* src){
    asm volatile("cp.async.cg.shared.global [%0], [%1], 16;" :: "r"(dst), "l"(src));
}
#define CP_COMMIT() asm volatile("cp.async.commit_group;" ::: "memory")
#define CP_WAIT1()  asm volatile("cp.async.wait_group 1;" ::: "memory")
#define CP_WAIT0()  asm volatile("cp.async.wait_group 0;" ::: "memory")
__device__ __forceinline__ void ldm_x4(uint32_t& r0, uint32_t& r1, uint32_t& r2, uint32_t& r3,
                                       uint32_t a){
    asm volatile("ldmatrix.sync.aligned.m8n8.x4.shared.b16 {%0,%1,%2,%3}, [%4];"
                 : "=r"(r0), "=r"(r1), "=r"(r2), "=r"(r3) : "r"(a));
}
__device__ __forceinline__ void ldm_x4t(uint32_t& r0, uint32_t& r1, uint32_t& r2, uint32_t& r3,
                                        uint32_t a){
    asm volatile("ldmatrix.sync.aligned.m8n8.x4.trans.shared.b16 {%0,%1,%2,%3}, [%4];"
                 : "=r"(r0), "=r"(r1), "=r"(r2), "=r"(r3) : "r"(a));
}
__device__ __forceinline__ void mma_step(float acc[2][4][4],
                                         const uint32_t af[2][4], const uint32_t bf[4][2],
                                         int MTn) {
    #pragma unroll
    for (int nt = 0; nt < 4; nt++)
        #pragma unroll
        for (int mt = 0; mt < 2; mt++)
            if (mt < MTn)
                mma16(acc[mt][nt][0], acc[mt][nt][1], acc[mt][nt][2], acc[mt][nt][3],
                      af[mt][0], af[mt][1], af[mt][2], af[mt][3], bf[nt][0], bf[nt][1]);
}

// ============ K=128 multi-tile machinery ========================================
// 128-row x 128-col K-contig tile copy: 2048 16B chunks, 256B/row, XOR swizzle.
__device__ __forceinline__ void cp_tile128(uint32_t dstb, const __half* __restrict__ g,
                                           int ld, int tid){
    #pragma unroll
    for (int j = 0; j < 4; j++) {
        int i = tid + j*NTHR;
        int r = i >> 4, c = i & 15;
        cp16(dstb + (uint32_t)(r*256 + ((c ^ (r & 7)) << 4)), g + (size_t)r*ld + c*8);
    }
}
// compute 128x128x128 from resident smem tiles (Ab rows m, Bb: BL=0 rows k / BL=1 rows n)
template<int BL>
__device__ __forceinline__ void compute_k128(uint32_t Ab, uint32_t Bb, float acc[2][4][4],
                                             int wm, int wn, int lane){
    const int rl = lane & 7, half = (lane >> 3) & 1, kc = lane >> 4;
    uint32_t af[2][4], bf[4][2];
    #pragma unroll
    for (int ks = 0; ks < 8; ks++) {
        #pragma unroll
        for (int mt = 0; mt < 2; mt++) {
            int row = wm*32 + mt*16 + half*8 + rl;
            uint32_t addr = Ab + row*256 + ((((ks << 1) | kc) ^ rl) << 4);
            ldm_x4(af[mt][0], af[mt][1], af[mt][2], af[mt][3], addr);
        }
        if (BL == 0) {
            int row = 16*ks + 8*kc + rl;
            #pragma unroll
            for (int ntp = 0; ntp < 2; ntp++) {
                int cn = wn*4 + ntp*2 + half;
                uint32_t addr = Bb + row*256 + (((uint32_t)(cn ^ rl)) << 4);
                ldm_x4t(bf[2*ntp][0], bf[2*ntp+1][0], bf[2*ntp][1], bf[2*ntp+1][1], addr);
            }
        } else {
            #pragma unroll
            for (int ntp = 0; ntp < 2; ntp++) {
                int row = wn*32 + ntp*16 + half*8 + rl;
                uint32_t addr = Bb + row*256 + ((((ks << 1) | kc) ^ rl) << 4);
                ldm_x4(bf[2*ntp][0], bf[2*ntp+1][0], bf[2*ntp][1], bf[2*ntp+1][1], addr);
            }
        }
        mma_step(acc, af, bf, 2);
    }
}

// ============ 3-stage BK=64 pipelined core (K=512 GEMMs) ========================
template<int AL, int MT>
__device__ __forceinline__ void cpA3(uint32_t dstb, const __half* __restrict__ Ag, int lda,
                                     int k0, int tid){
    #pragma unroll
    for (int j = 0; j < MT; j++) {
        int i = tid + j*NTHR;
        if (AL == 0) { int m = i >> 3, c = i & 7;
            cp16(dstb + (uint32_t)(m*128 + ((c ^ (m & 7)) << 4)),
                 Ag + (size_t)m*lda + k0 + c*8); }
        else         { int r = i >> 4, c = i & 15;
            cp16(dstb + (uint32_t)(r*256 + ((c ^ (r & 7)) << 4)),
                 Ag + (size_t)(k0 + r)*lda + c*8); }
    }
}
__device__ __forceinline__ void cpB3(uint32_t dstb, const __half* __restrict__ Bg, int ldb,
                                     int k0, int tid){
    #pragma unroll
    for (int j = 0; j < 2; j++) {
        int i = tid + j*NTHR;
        int r = i >> 4, c = i & 15;
        cp16(dstb + (uint32_t)(r*256 + ((c ^ (r & 7)) << 4)),
             Bg + (size_t)(k0 + r)*ldb + c*8);
    }
}
template<int AL, int MT>
__device__ __forceinline__ void ldfA3(uint32_t Ab, int ks, int wm, int lane,
                                      uint32_t af[2][4]){
    int rl = lane & 7;
    if (AL == 0) {
        int half = (lane >> 3) & 1, kc = lane >> 4;
        #pragma unroll
        for (int mt = 0; mt < MT; mt++) {
            int row = wm*(16*MT) + mt*16 + half*8 + rl;
            uint32_t addr = Ab + row*128 + ((((ks << 1) | kc) ^ rl) << 4);
            ldm_x4(af[mt][0], af[mt][1], af[mt][2], af[mt][3], addr);
        }
    } else {
        int sel = (lane >> 3) & 1, kh = lane >> 4;
        int row = 16*ks + 8*kh + rl;
        #pragma unroll
        for (int mt = 0; mt < MT; mt++) {
            int cm = wm*(2*MT) + mt*2 + sel;
            uint32_t addr = Ab + row*256 + (((uint32_t)(cm ^ rl)) << 4);
            ldm_x4t(af[mt][0], af[mt][1], af[mt][2], af[mt][3], addr);
        }
    }
}
__device__ __forceinline__ void ldfB3(uint32_t Bb, int ks, int wn, int lane,
                                      uint32_t bf[4][2]){
    int rl = lane & 7;
    int sel = (lane >> 3) & 1, kh = lane >> 4;
    int row = 16*ks + 8*kh + rl;
    #pragma unroll
    for (int ntp = 0; ntp < 2; ntp++) {
        int cn = wn*4 + ntp*2 + sel;
        uint32_t addr = Bb + row*256 + (((uint32_t)(cn ^ rl)) << 4);
        ldm_x4t(bf[2*ntp][0], bf[2*ntp+1][0], bf[2*ntp][1], bf[2*ntp+1][1], addr);
    }
}
template<int AL, int NCH, int MT>
__device__ __forceinline__ void mma_core_3s(const __half* __restrict__ Ag, int lda,
                                            const __half* __restrict__ Bg, int ldb,
                                            float acc[2][4][4], char* smraw) {
    const int tid = threadIdx.x, lane = tid & 31;
    const int wid = tid >> 5, wm = wid & 3, wn = wid >> 2;
    constexpr uint32_t ABYTES = MT*8192u;
    constexpr uint32_t STGB   = ABYTES + 16384u;
    const uint32_t sb = smem_u32(smraw);

    cpA3<AL,MT>(sb, Ag, lda, 0, tid);
    cpB3(sb + ABYTES, Bg, ldb, 0, tid);
    CP_COMMIT();
    cpA3<AL,MT>(sb + STGB, Ag, lda, 64, tid);
    cpB3(sb + STGB + ABYTES, Bg, ldb, 64, tid);
    CP_COMMIT();

    uint32_t af[2][4], bf[4][2];
    int cur = 0, nxt2 = 2;
    #pragma unroll 1
    for (int c = 0; c < NCH; c++) {
        CP_WAIT1();
        __syncthreads();
        if (c + 2 < NCH) {
            uint32_t ns = sb + (uint32_t)nxt2*STGB;
            cpA3<AL,MT>(ns, Ag, lda, (c+2)*64, tid);
            cpB3(ns + ABYTES, Bg, ldb, (c+2)*64, tid);
        }
        CP_COMMIT();
        uint32_t Ab = sb + (uint32_t)cur*STGB;
        uint32_t Bb = Ab + ABYTES;
        #pragma unroll
        for (int ks = 0; ks < 4; ks++) {
            ldfA3<AL,MT>(Ab, ks, wm, lane, af);
            ldfB3(Bb, ks, wn, lane, bf);
            mma_step(acc, af, bf, MT);
        }
        cur++;  if (cur == 3) cur = 0;
        nxt2++; if (nxt2 == 3) nxt2 = 0;
    }
    __syncthreads();
}

#define SMEM_MT   98304   // resident B 32KB + 2 x A 32KB
#define SMEM_3S2  98304   // MT=2: 3 * 32KB
#define SMEM_3S1  73728   // MT=1: 3 * 24KB

// epilogue index helpers
#define ROW128(mt, h)  (wm*32 + (mt)*16 + group + 8*(h))
#define ROW64(h)       (wm*16 + group + 8*(h))
#define COL_OF(nt)     (wn*32 + (nt)*8 + 2*tg)

// ---------------- input conversion fp32 -> fp16 ----------------
__global__ void k_half(const float* __restrict__ seq, const float* __restrict__ wk,
                       const float* __restrict__ wv,  const float* __restrict__ wq,
                       const float* __restrict__ w1,  const float* __restrict__ w2) {
    int i4 = blockIdx.x*256 + threadIdx.x;
    const float4* src; __half* dst; int off;
    if      (i4 < 524288) { src = (const float4*)seq; dst = g_seqH; off = i4; }
    else if (i4 < 528384) { src = (const float4*)wk;  dst = g_wkH;  off = i4 - 524288; }
    else if (i4 < 532480) { src = (const float4*)wv;  dst = g_wvH;  off = i4 - 528384; }
    else if (i4 < 536576) { src = (const float4*)wq;  dst = g_wqH;  off = i4 - 532480; }
    else if (i4 < 552960) { src = (const float4*)w1;  dst = g_w1H;  off = i4 - 536576; }
    else if (i4 < 569344) { src = (const float4*)w2;  dst = g_w2H;  off = i4 - 552960; }
    else return;
    float4 v = src[off];
    uint2 o;
    o.x = h2pack(v.x, v.y);
    o.y = h2pack(v.z, v.w);
    *reinterpret_cast<uint2*>(dst + off*4) = o;
}

// ---------------- scalar kernels ----------------
__device__ __forceinline__ float bred128(float v){
    __shared__ float wr[4];
    #pragma unroll
    for (int o = 16; o > 0; o >>= 1) v += __shfl_down_sync(0xffffffffu, v, o);
    int tid = threadIdx.x;
    if ((tid & 31) == 0) wr[tid >> 5] = v;
    __syncthreads();
    float r = wr[0] + wr[1] + wr[2] + wr[3];
    __syncthreads();
    return r;
}
__global__ void k_dots(const float* __restrict__ seq,
                       const float* __restrict__ wlr,  const float* __restrict__ blr,
                       const float* __restrict__ wdec, const float* __restrict__ bdec,
                       const float* __restrict__ wmom, const float* __restrict__ bmom) {
    int b = blockIdx.x >> 6, c = blockIdx.x & 63;
    int tid = threadIdx.x;
    float x = seq[((size_t)b*4096 + c*64)*D + tid];
    float s1 = bred128(x*wlr[tid]);
    float s2 = bred128(x*wdec[tid]);
    float s3 = bred128(x*wmom[tid]);
    if (tid == 0) {
        g_lrv [b*NC + c] = sigm(s1 + blr[0]);
        g_keep[b*NC + c] = 1.f - sigm(s2 + bdec[0]);
        g_eta [b*NC + c] = sigm(s3 + bmom[0]);
    }
}
__global__ void k_coef() {
    int b = threadIdx.x;
    if (b >= BATCH) return;
    float Av = 1.f, Bv = 1.f;
    g_coef[b*NC + NC-1] = -g_lrv[b*NC + NC-1]*(2.f/128.f);
    for (int j = NC-2; j >= 0; j--) {
        Bv *= g_keep[b*NC + j+1];
        Av  = Bv + g_eta[b*NC + j+1]*Av;
        g_coef[b*NC + j] = -Av*g_lrv[b*NC + j]*(2.f/128.f);
    }
}

// ---------------- G1: K/V/Q = seq @ W  (resident W, 2 row tiles/CTA) ------------
__global__ __launch_bounds__(NTHR, 2) void g1_proj() {
    extern __shared__ char smraw[];
    const uint32_t sb = smem_u32(smraw);
    const __half* W = (blockIdx.z == 0) ? g_wkH : (blockIdx.z == 1 ? g_wvH : g_wqH);
    const int tid = threadIdx.x, lane = tid & 31, group = lane >> 2, tg = lane & 3;
    const int wid = tid >> 5, wm = wid & 3, wn = wid >> 2;
    int row0 = blockIdx.x * 256;
    cp_tile128(sb, W, D, tid);
    cp_tile128(sb + 32768u, g_seqH + (size_t)row0*D, D, tid);
    CP_COMMIT();
    cp_tile128(sb + 65536u, g_seqH + (size_t)(row0 + 128)*D, D, tid);
    CP_COMMIT();
    float* Of = (blockIdx.z == 0) ? g_K : (blockIdx.z == 1 ? g_V : g_Q);
    __half* Oh = (blockIdx.z == 0) ? g_KH : (blockIdx.z == 2 ? g_QH : nullptr);
    #pragma unroll
    for (int t = 0; t < 2; t++) {
        if (t == 0) CP_WAIT1(); else CP_WAIT0();
        __syncthreads();
        float acc[2][4][4] = {};
        compute_k128<0>(sb + 32768u + (uint32_t)t*32768u, sb, acc, wm, wn, lane);
        int rb = row0 + t*128;
        #pragma unroll
        for (int mt = 0; mt < 2; mt++)
            #pragma unroll
            for (int h = 0; h < 2; h++) {
                int tok = rb + ROW128(mt, h);
                #pragma unroll
                for (int nt = 0; nt < 4; nt++) {
                    int cc = COL_OF(nt);
                    float v0 = acc[mt][nt][2*h], v1 = acc[mt][nt][2*h+1];
                    *reinterpret_cast<float2*>(Of + (size_t)tok*D + cc) = make_float2(v0, v1);
                    if (Oh)
                        *reinterpret_cast<uint32_t*>(Oh + (size_t)tok*D + cc) = h2pack(v0, v1);
                }
            }
    }
}

// ---------------- G2: Z = K @ w1 -> gelu (resident w1 slice, 2 tiles/CTA) -------
__global__ __launch_bounds__(NTHR, 2) void g2_zgelu() {
    extern __shared__ char smraw[];
    const uint32_t sb = smem_u32(smraw);
    const int tid = threadIdx.x, lane = tid & 31, group = lane >> 2, tg = lane & 3;
    const int wid = tid >> 5, wm = wid & 3, wn = wid >> 2;
    int row0 = blockIdx.x * 256, n0 = blockIdx.y * 128;
    cp_tile128(sb, g_w1H + n0, HID, tid);
    cp_tile128(sb + 32768u, g_KH + (size_t)row0*D, D, tid);
    CP_COMMIT();
    cp_tile128(sb + 65536u, g_KH + (size_t)(row0 + 128)*D, D, tid);
    CP_COMMIT();
    #pragma unroll
    for (int t = 0; t < 2; t++) {
        if (t == 0) CP_WAIT1(); else CP_WAIT0();
        __syncthreads();
        float acc[2][4][4] = {};
        compute_k128<0>(sb + 32768u + (uint32_t)t*32768u, sb, acc, wm, wn, lane);
        int rb = row0 + t*128;
        #pragma unroll
        for (int mt = 0; mt < 2; mt++)
            #pragma unroll
            for (int h = 0; h < 2; h++) {
                int tok = rb + ROW128(mt, h);
                size_t base = (size_t)tok*HID + n0;
                #pragma unroll
                for (int nt = 0; nt < 4; nt++) {
                    int cc = COL_OF(nt);
                    float a0, p0, a1, p1;
                    gelu_both(acc[mt][nt][2*h],   a0, p0);
                    gelu_both(acc[mt][nt][2*h+1], a1, p1);
                    *reinterpret_cast<uint32_t*>(g_AH + base + cc) = h2pack(a0, a1);
                    *reinterpret_cast<float2*>(g_GP + base + cc) = make_float2(p0, p1);
                }
            }
    }
}

// ---------------- G3: H = A @ w2; rmsnorm bwd (64-row tiles) ----------------
__global__ __launch_bounds__(NTHR, 2) void g3_hback(const float* __restrict__ gamma) {
    extern __shared__ char smraw[];
    __shared__ float gam[128];
    const int tid = threadIdx.x;
    if (tid < 128) gam[tid] = gamma[tid];
    int row0 = blockIdx.x * 64;
    float acc[2][4][4] = {};
    mma_core_3s<0,8,1>(g_AH + (size_t)row0*HID, HID, g_w2H, D, acc, smraw);
    const int lane = tid & 31, group = lane >> 2, tg = lane & 3;
    const int wid = tid >> 5, wm = wid & 3, wn = wid >> 2;
    float* rs = reinterpret_cast<float*>(smraw);        // [4][64]
    float* cs = reinterpret_cast<float*>(smraw) + 256;  // [4][128]

    #pragma unroll
    for (int h = 0; h < 2; h++) {
        float s = 0;
        #pragma unroll
        for (int nt = 0; nt < 4; nt++)
            s += acc[0][nt][2*h]*acc[0][nt][2*h] + acc[0][nt][2*h+1]*acc[0][nt][2*h+1];
        s += __shfl_xor_sync(0xffffffffu, s, 1);
        s += __shfl_xor_sync(0xffffffffu, s, 2);
        if (tg == 0) rs[wn*64 + ROW64(h)] = s;
    }
    __syncthreads();
    float ir[2], cf[2];
    #pragma unroll
    for (int h = 0; h < 2; h++) {
        int r = ROW64(h);
        float s = rs[r] + rs[64 + r] + rs[128 + r] + rs[192 + r];
        ir[h] = rsqrtf(s*(1.f/128.f) + 1e-6f);
        int tok = row0 + r;
        cf[h] = g_coef[(tok >> 12)*NC + ((tok & 4095) >> 6)];
    }
    __syncthreads();

    #pragma unroll
    for (int h = 0; h < 2; h++) {
        int r = ROW64(h), tok = row0 + r;
        float irr = ir[h], cfv = cf[h];
        float dsum = 0;
        #pragma unroll
        for (int nt = 0; nt < 4; nt++) {
            int cc = COL_OF(nt);
            float2 kk = *reinterpret_cast<const float2*>(g_K + (size_t)tok*D + cc);
            float2 vv = *reinterpret_cast<const float2*>(g_V + (size_t)tok*D + cc);
            float hn0 = acc[0][nt][2*h]*irr,   hn1 = acc[0][nt][2*h+1]*irr;
            float dp0 = cfv*(hn0*gam[cc] + kk.x - vv.x);
            float dp1 = cfv*(hn1*gam[cc+1] + kk.y - vv.y);
            dsum += dp0*gam[cc]*hn0 + dp1*gam[cc+1]*hn1;
        }
        dsum += __shfl_xor_sync(0xffffffffu, dsum, 1);
        dsum += __shfl_xor_sync(0xffffffffu, dsum, 2);
        if (tg == 0) rs[wn*64 + r] = dsum;
    }
    __syncthreads();

    float colp[4][2] = {};
    #pragma unroll
    for (int h = 0; h < 2; h++) {
        int r = ROW64(h), tok = row0 + r;
        float irr = ir[h], cfv = cf[h];
        float rd = (rs[r] + rs[64 + r] + rs[128 + r] + rs[192 + r])*(1.f/128.f);
        #pragma unroll
        for (int nt = 0; nt < 4; nt++) {
            int cc = COL_OF(nt);
            float2 kk = *reinterpret_cast<const float2*>(g_K + (size_t)tok*D + cc);
            float2 vv = *reinterpret_cast<const float2*>(g_V + (size_t)tok*D + cc);
            float hn0 = acc[0][nt][2*h]*irr,   hn1 = acc[0][nt][2*h+1]*irr;
            float dp0 = cfv*(hn0*gam[cc] + kk.x - vv.x);
            float dp1 = cfv*(hn1*gam[cc+1] + kk.y - vv.y);
            float o0 = irr*(dp0*gam[cc]   - hn0*rd);
            float o1 = irr*(dp1*gam[cc+1] - hn1*rd);
            *reinterpret_cast<uint32_t*>(g_dHH + (size_t)tok*D + cc) = h2pack(o0, o1);
            colp[nt][0] += dp0*hn0;
            colp[nt][1] += dp1*hn1;
        }
    }
    __syncthreads();
    #pragma unroll
    for (int nt = 0; nt < 4; nt++)
        #pragma unroll
        for (int j = 0; j < 2; j++) {
            float v = colp[nt][j];
            v += __shfl_xor_sync(0xffffffffu, v, 4);
            v += __shfl_xor_sync(0xffffffffu, v, 8);
            v += __shfl_xor_sync(0xffffffffu, v, 16);
            if (group == 0) cs[wm*128 + COL_OF(nt) + j] = v;
        }
    __syncthreads();
    const int t = threadIdx.x;
    if (t < 128) {
        float s = cs[t] + cs[128 + t] + cs[256 + t] + cs[384 + t];
        g_gfp[blockIdx.x*128 + t] = s;
    }
}

// ---------------- G4: dZ = (dH @ w2^T) * GP (resident w2 slice, 2 tiles) --------
__global__ __launch_bounds__(NTHR, 2) void g4_da() {
    extern __shared__ char smraw[];
    const uint32_t sb = smem_u32(smraw);
    const int tid = threadIdx.x, lane = tid & 31, group = lane >> 2, tg = lane & 3;
    const int wid = tid >> 5, wm = wid & 3, wn = wid >> 2;
    int row0 = blockIdx.x * 256, n0 = blockIdx.y * 128;
    cp_tile128(sb, g_w2H + (size_t)n0*D, D, tid);
    cp_tile128(sb + 32768u, g_dHH + (size_t)row0*D, D, tid);
    CP_COMMIT();
    cp_tile128(sb + 65536u, g_dHH + (size_t)(row0 + 128)*D, D, tid);
    CP_COMMIT();
    #pragma unroll
    for (int t = 0; t < 2; t++) {
        if (t == 0) CP_WAIT1(); else CP_WAIT0();
        __syncthreads();
        float acc[2][4][4] = {};
        compute_k128<1>(sb + 32768u + (uint32_t)t*32768u, sb, acc, wm, wn, lane);
        int rb = row0 + t*128;
        #pragma unroll
        for (int mt = 0; mt < 2; mt++)
            #pragma unroll
            for (int h = 0; h < 2; h++) {
                int tok = rb + ROW128(mt, h);
                size_t base = (size_t)tok*HID + n0;
                #pragma unroll
                for (int nt = 0; nt < 4; nt++) {
                    int cc = COL_OF(nt);
                    float2 gp = *reinterpret_cast<const float2*>(g_GP + base + cc);
                    *reinterpret_cast<uint32_t*>(g_dZH + base + cc) =
                        h2pack(acc[mt][nt][2*h]*gp.x, acc[mt][nt][2*h+1]*gp.y);
                }
            }
    }
}

// ---------------- G5 merged: y=0 w1p = K^T@dZ ; y=1 w2p = A^T@dH ----------------
__global__ __launch_bounds__(NTHR, 2) void g5_wp() {
    extern __shared__ char smraw[];
    int z = blockIdx.z, bh = z >> 3, sl = z & 7;
    int t0 = bh*4096 + sl*512;
    const __half* Ag; const __half* Bg; int lda, ldb;
    if (blockIdx.y == 0) {
        Ag = g_KH + (size_t)t0*D;                     lda = D;
        Bg = g_dZH + (size_t)t0*HID + blockIdx.x*128; ldb = HID;
    } else {
        Ag = g_AH + (size_t)t0*HID + blockIdx.x*128;  lda = HID;
        Bg = g_dHH + (size_t)t0*D;                    ldb = D;
    }
    float acc[2][4][4] = {};
    mma_core_3s<1,8,2>(Ag, lda, Bg, ldb, acc, smraw);
    const int tid = threadIdx.x, lane = tid & 31, group = lane >> 2, tg = lane & 3;
    const int wid = tid >> 5, wm = wid & 3, wn = wid >> 2;
    if (blockIdx.y == 0) {
        float* C = g_w1p + (size_t)z*(D*HID);
        int n0 = blockIdx.x * 128;
        #pragma unroll
        for (int mt = 0; mt < 2; mt++)
            #pragma unroll
            for (int h = 0; h < 2; h++) {
                int r = ROW128(mt, h);
                #pragma unroll
                for (int nt = 0; nt < 4; nt++)
                    *reinterpret_cast<float2*>(C + (size_t)r*HID + n0 + COL_OF(nt)) =
                        make_float2(acc[mt][nt][2*h], acc[mt][nt][2*h+1]);
            }
    } else {
        float* C = g_w2p + (size_t)z*(HID*D);
        int m0 = blockIdx.x * 128;
        #pragma unroll
        for (int mt = 0; mt < 2; mt++)
            #pragma unroll
            for (int h = 0; h < 2; h++) {
                int r = m0 + ROW128(mt, h);
                #pragma unroll
                for (int nt = 0; nt < 4; nt++)
                    *reinterpret_cast<float2*>(C + (size_t)r*D + COL_OF(nt)) =
                        make_float2(acc[mt][nt][2*h], acc[mt][nt][2*h+1]);
            }
    }
}

// ---------------- reduce split-K partials -> half finals + dgamma --------------
__global__ void k_reduce() {
    int i = blockIdx.x*256 + threadIdx.x;
    if (i < BATCH*D*HID) {
        int bh = i >> 16, off = i & 65535;
        float s1 = 0, s2 = 0;
        #pragma unroll
        for (int s = 0; s < SLICES; s++) {
            s1 += g_w1p[(size_t)(bh*SLICES + s)*(D*HID) + off];
            s2 += g_w2p[(size_t)(bh*SLICES + s)*(HID*D) + off];
        }
        g_w1fH[i] = __float2half_rn(s1);
        g_w2fH[i] = __float2half_rn(s2);
    }
    if (i < BATCH*D) {
        int bh = i >> 7, col = i & 127;
        float s = 0;
        #pragma unroll
        for (int q = 0; q < 64; q++) s += g_gfp[(bh*64 + q)*128 + col];
        g_gf[i] = s;
    }
}

// ---------------- G6: A2 = gelu(Q @ w1f) (resident w1f slice, 2 tiles) ----------
__global__ __launch_bounds__(NTHR, 2) void g6_z2() {
    extern __shared__ char smraw[];
    const uint32_t sb = smem_u32(smraw);
    const int tid = threadIdx.x, lane = tid & 31, group = lane >> 2, tg = lane & 3;
    const int wid = tid >> 5, wm = wid & 3, wn = wid >> 2;
    int row0 = blockIdx.x * 256, n0 = blockIdx.y * 128;
    int bh = row0 >> 12;
    cp_tile128(sb, g_w1fH + (size_t)bh*(D*HID) + n0, HID, tid);
    cp_tile128(sb + 32768u, g_QH + (size_t)row0*D, D, tid);
    CP_COMMIT();
    cp_tile128(sb + 65536u, g_QH + (size_t)(row0 + 128)*D, D, tid);
    CP_COMMIT();
    #pragma unroll
    for (int t = 0; t < 2; t++) {
        if (t == 0) CP_WAIT1(); else CP_WAIT0();
        __syncthreads();
        float acc[2][4][4] = {};
        compute_k128<0>(sb + 32768u + (uint32_t)t*32768u, sb, acc, wm, wn, lane);
        int rb = row0 + t*128;
        #pragma unroll
        for (int mt = 0; mt < 2; mt++)
            #pragma unroll
            for (int h = 0; h < 2; h++) {
                int tok = rb + ROW128(mt, h);
                size_t base = (size_t)tok*HID + n0;
                #pragma unroll
                for (int nt = 0; nt < 4; nt++) {
                    int cc = COL_OF(nt);
                    *reinterpret_cast<uint32_t*>(g_A2H + base + cc) =
                        h2pack(gelu_f(acc[mt][nt][2*h]), gelu_f(acc[mt][nt][2*h+1]));
                }
            }
    }
}

// ---------------- G7: out = rmsnorm(A2 @ w2f)*gf + Q (64-row tiles) -------------
__global__ __launch_bounds__(NTHR, 2) void g7_out(float* __restrict__ out) {
    extern __shared__ char smraw[];
    __shared__ float gfs[128];
    const int tid = threadIdx.x;
    int row0 = blockIdx.x * 64;
    int bh = row0 >> 12;
    if (tid < 128) gfs[tid] = g_gf[bh*D + tid];
    float acc[2][4][4] = {};
    mma_core_3s<0,8,1>(g_A2H + (size_t)row0*HID, HID, g_w2fH + (size_t)bh*(HID*D), D, acc, smraw);
    const int lane = tid & 31, group = lane >> 2, tg = lane & 3;
    const int wid = tid >> 5, wm = wid & 3, wn = wid >> 2;
    float* rs = reinterpret_cast<float*>(smraw);  // [4][64]
    #pragma unroll
    for (int h = 0; h < 2; h++) {
        float s = 0;
        #pragma unroll
        for (int nt = 0; nt < 4; nt++)
            s += acc[0][nt][2*h]*acc[0][nt][2*h] + acc[0][nt][2*h+1]*acc[0][nt][2*h+1];
        s += __shfl_xor_sync(0xffffffffu, s, 1);
        s += __shfl_xor_sync(0xffffffffu, s, 2);
        if (tg == 0) rs[wn*64 + ROW64(h)] = s;
    }
    __syncthreads();
    #pragma unroll
    for (int h = 0; h < 2; h++) {
        int r = ROW64(h), tok = row0 + r;
        float s = rs[r] + rs[64 + r] + rs[128 + r] + rs[192 + r];
        float irr = rsqrtf(s*(1.f/128.f) + 1e-6f);
        #pragma unroll
        for (int nt = 0; nt < 4; nt++) {
            int cc = COL_OF(nt);
            float2 qq = *reinterpret_cast<const float2*>(g_Q + (size_t)tok*D + cc);
            *reinterpret_cast<float2*>(out + (size_t)tok*D + cc) =
                make_float2(acc[0][nt][2*h]*irr*gfs[cc] + qq.x,
                            acc[0][nt][2*h+1]*irr*gfs[cc+1] + qq.y);
        }
    }
}

// ---------------- launch ----------------
extern "C" void kernel_launch(void* const* d_in, const int* in_sizes, int n_in,
                              void* d_out, int out_size) {
    (void)in_sizes; (void)n_in; (void)out_size;
    const float* seq  = (const float*)d_in[0];
    const float* wk   = (const float*)d_in[1];
    const float* wv   = (const float*)d_in[2];
    const float* wq   = (const float*)d_in[3];
    const float* wlr  = (const float*)d_in[4];
    const float* blr  = (const float*)d_in[5];
    const float* wdec = (const float*)d_in[6];
    const float* bdec = (const float*)d_in[7];
    const float* wmom = (const float*)d_in[8];
    const float* bmom = (const float*)d_in[9];
    const float* gamma= (const float*)d_in[10];
    const float* w1   = (const float*)d_in[11];
    const float* w2   = (const float*)d_in[12];
    float* out = (float*)d_out;

    cudaFuncSetAttribute(g1_proj,  cudaFuncAttributeMaxDynamicSharedMemorySize, SMEM_MT);
    cudaFuncSetAttribute(g2_zgelu, cudaFuncAttributeMaxDynamicSharedMemorySize, SMEM_MT);
    cudaFuncSetAttribute(g3_hback, cudaFuncAttributeMaxDynamicSharedMemorySize, SMEM_3S1);
    cudaFuncSetAttribute(g4_da,    cudaFuncAttributeMaxDynamicSharedMemorySize, SMEM_MT);
    cudaFuncSetAttribute(g5_wp,    cudaFuncAttributeMaxDynamicSharedMemorySize, SMEM_3S2);
    cudaFuncSetAttribute(g6_z2,    cudaFuncAttributeMaxDynamicSharedMemorySize, SMEM_MT);
    cudaFuncSetAttribute(g7_out,   cudaFuncAttributeMaxDynamicSharedMemorySize, SMEM_3S1);

    k_half  <<<2224, 256>>>(seq, wk, wv, wq, w1, w2);
    k_dots  <<<BATCH*NC, 128>>>(seq, wlr, blr, wdec, bdec, wmom, bmom);
    k_coef  <<<1, 32>>>();
    g1_proj <<<dim3(NTOK/256, 1, 3), NTHR, SMEM_MT>>>();
    g2_zgelu<<<dim3(NTOK/256, HID/128), NTHR, SMEM_MT>>>();
    g3_hback<<<NTOK/64, NTHR, SMEM_3S1>>>(gamma);
    g4_da   <<<dim3(NTOK/256, HID/128), NTHR, SMEM_MT>>>();
    g5_wp   <<<dim3(HID/128, 2, BATCH*SLICES), NTHR, SMEM_3S2>>>();
    k_reduce<<<(BATCH*D*HID)/256, 256>>>();
    g6_z2   <<<dim3(NTOK/256, HID/128), NTHR, SMEM_MT>>>();
    g7_out  <<<NTOK/64, NTHR, SMEM_3S1>>>(out);
}

// round 13
// speedup vs baseline: 1.0391x; 1.0391x over previous
#include <cuda_runtime.h>
#include <cuda_fp16.h>
#include <stdint.h>
#include <math.h>

// dims: b=4, n=4096, d=128, hid=512, CHUNK=64
#define NTOK 16384
#define D 128
#define HID 512
#define NC 64
#define BATCH 4
#define SLICES 8
#define NTHR 512

// ---------------- scratch ----------------
__device__ float  g_K [NTOK*D];
__device__ float  g_V [NTOK*D];
__device__ float  g_Q [NTOK*D];
__device__ __half g_GPH[NTOK*HID];   // gelu' stored fp16 (saves 34MB traffic)
__device__ __half g_seqH[NTOK*D];
__device__ __half g_wkH[D*D], g_wvH[D*D], g_wqH[D*D];
__device__ __half g_w1H[D*HID];
__device__ __half g_w2H[HID*D];
__device__ __half g_KH [NTOK*D];
__device__ __half g_QH [NTOK*D];
__device__ __half g_AH [NTOK*HID];
__device__ __half g_dHH[NTOK*D];
__device__ __half g_dZH[NTOK*HID];
__device__ __half g_A2H[NTOK*HID];
__device__ __half g_w1fH[BATCH*D*HID];
__device__ __half g_w2fH[BATCH*HID*D];
__device__ float  g_lrv [BATCH*NC];
__device__ float  g_keep[BATCH*NC];
__device__ float  g_eta [BATCH*NC];
__device__ float  g_coef[BATCH*NC];
__device__ float  g_gfp[256*D];
__device__ float  g_gf [BATCH*D];
__device__ float  g_w1p[BATCH*SLICES*D*HID];
__device__ float  g_w2p[BATCH*SLICES*HID*D];

// ---------------- helpers ----------------
__device__ __forceinline__ float sigm(float x){ return 1.f/(1.f+expf(-x)); }
__device__ __forceinline__ float tanh_fast(float u){
    float e = __expf(2.f*u);
    return 1.f - __fdividef(2.f, e + 1.f);
}
__device__ __forceinline__ void gelu_both(float x, float& a, float& gp){
    const float c0 = 0.7978845608028654f, c1 = 0.044715f;
    float x2 = x*x;
    float t = tanh_fast(c0*x*(1.f + c1*x2));
    a  = 0.5f*x*(1.f + t);
    gp = 0.5f*(1.f + t) + 0.5f*x*(1.f - t*t)*c0*(1.f + 3.f*c1*x2);
}
__device__ __forceinline__ float gelu_f(float x){
    float t = tanh_fast(0.7978845608028654f*x*(1.f + 0.044715f*x*x));
    return 0.5f*x*(1.f + t);
}
__device__ __forceinline__ uint32_t h2pack(float lo, float hi){
    __half2 h = __floats2half2_rn(lo, hi);
    return *reinterpret_cast<uint32_t*>(&h);
}
__device__ __forceinline__ void mma16(float& c0, float& c1, float& c2, float& c3,
                                      uint32_t a0, uint32_t a1, uint32_t a2, uint32_t a3,
                                      uint32_t b0, uint32_t b1){
    asm volatile("mma.sync.aligned.m16n8k16.row.col.f32.f16.f16.f32 "
                 "{%0,%1,%2,%3}, {%4,%5,%6,%7}, {%8,%9}, {%0,%1,%2,%3};"
                 : "+f"(c0), "+f"(c1), "+f"(c2), "+f"(c3)
                 : "r"(a0), "r"(a1), "r"(a2), "r"(a3), "r"(b0), "r"(b1));
}
__device__ __forceinline__ uint32_t smem_u32(const void* p){
    uint32_t a;
    asm("{ .reg .u64 t; cvta.to.shared.u64 t, %1; cvt.u32.u64 %0, t; }" : "=r"(a) : "l"(p));
    return a;
}
__device__ __forceinline__ void cp16(uint32_t dst, const void* src){
    asm volatile("cp.async.cg.shared.global [%0], [%1], 16;" :: "r"(dst), "l"(src));
}
#define CP_COMMIT() asm volatile("cp.async.commit_group;" ::: "memory")
#define CP_WAIT1()  asm volatile("cp.async.wait_group 1;" ::: "memory")
__device__ __forceinline__ void ldm_x4(uint32_t& r0, uint32_t& r1, uint32_t& r2, uint32_t& r3,
                                       uint32_t a){
    asm volatile("ldmatrix.sync.aligned.m8n8.x4.shared.b16 {%0,%1,%2,%3}, [%4];"
                 : "=r"(r0), "=r"(r1), "=r"(r2), "=r"(r3) : "r"(a));
}
__device__ __forceinline__ void ldm_x4t(uint32_t& r0, uint32_t& r1, uint32_t& r2, uint32_t& r3,
                                        uint32_t a){
    asm volatile("ldmatrix.sync.aligned.m8n8.x4.trans.shared.b16 {%0,%1,%2,%3}, [%4];"
                 : "=r"(r0), "=r"(r1), "=r"(r2), "=r"(r3) : "r"(a));
}
__device__ __forceinline__ void mma_step(float acc[2][4][4],
                                         const uint32_t af[2][4], const uint32_t bf[4][2],
                                         int MTn) {
    #pragma unroll
    for (int nt = 0; nt < 4; nt++)
        #pragma unroll
        for (int mt = 0; mt < 2; mt++)
            if (mt < MTn)
                mma16(acc[mt][nt][0], acc[mt][nt][1], acc[mt][nt][2], acc[mt][nt][3],
                      af[mt][0], af[mt][1], af[mt][2], af[mt][3], bf[nt][0], bf[nt][1]);
}

// ============ unified 3-stage BK=64 pipelined core ==============================
// MT tiles of 64 rows each for A (MT=2: 128-row tile; MT=1: 64-row tile).
// AL=0: A gmem [m][k] k-contig, smem rows m 128B/row.
// AL=1: A gmem [k][m] m-contig, smem rows k 256B/row (free transpose; MT=2 only).
// BL=0: B gmem [k][n] n-contig, smem rows k 256B/row.
// BL=1: B gmem [n][k] k-contig, smem rows n 128B/row.
template<int AL, int MT>
__device__ __forceinline__ void cpA3(uint32_t dstb, const __half* __restrict__ Ag, int lda,
                                     int k0, int tid){
    #pragma unroll
    for (int j = 0; j < MT; j++) {
        int i = tid + j*NTHR;
        if (AL == 0) { int m = i >> 3, c = i & 7;
            cp16(dstb + (uint32_t)(m*128 + ((c ^ (m & 7)) << 4)),
                 Ag + (size_t)m*lda + k0 + c*8); }
        else         { int r = i >> 4, c = i & 15;
            cp16(dstb + (uint32_t)(r*256 + ((c ^ (r & 7)) << 4)),
                 Ag + (size_t)(k0 + r)*lda + c*8); }
    }
}
template<int BL>
__device__ __forceinline__ void cpB3(uint32_t dstb, const __half* __restrict__ Bg, int ldb,
                                     int k0, int tid){
    #pragma unroll
    for (int j = 0; j < 2; j++) {
        int i = tid + j*NTHR;
        if (BL == 0) { int r = i >> 4, c = i & 15;
            cp16(dstb + (uint32_t)(r*256 + ((c ^ (r & 7)) << 4)),
                 Bg + (size_t)(k0 + r)*ldb + c*8); }
        else         { int n = i >> 3, c = i & 7;
            cp16(dstb + (uint32_t)(n*128 + ((c ^ (n & 7)) << 4)),
                 Bg + (size_t)n*ldb + k0 + c*8); }
    }
}
template<int AL, int MT>
__device__ __forceinline__ void ldfA3(uint32_t Ab, int ks, int wm, int lane,
                                      uint32_t af[2][4]){
    int rl = lane & 7;
    if (AL == 0) {
        int half = (lane >> 3) & 1, kc = lane >> 4;
        #pragma unroll
        for (int mt = 0; mt < MT; mt++) {
            int row = wm*(16*MT) + mt*16 + half*8 + rl;
            uint32_t addr = Ab + row*128 + ((((ks << 1) | kc) ^ rl) << 4);
            ldm_x4(af[mt][0], af[mt][1], af[mt][2], af[mt][3], addr);
        }
    } else {
        int sel = (lane >> 3) & 1, kh = lane >> 4;
        int row = 16*ks + 8*kh + rl;
        #pragma unroll
        for (int mt = 0; mt < MT; mt++) {
            int cm = wm*(2*MT) + mt*2 + sel;
            uint32_t addr = Ab + row*256 + (((uint32_t)(cm ^ rl)) << 4);
            ldm_x4t(af[mt][0], af[mt][1], af[mt][2], af[mt][3], addr);
        }
    }
}
template<int BL>
__device__ __forceinline__ void ldfB3(uint32_t Bb, int ks, int wn, int lane,
                                      uint32_t bf[4][2]){
    int rl = lane & 7;
    if (BL == 0) {
        int sel = (lane >> 3) & 1, kh = lane >> 4;
        int row = 16*ks + 8*kh + rl;
        #pragma unroll
        for (int ntp = 0; ntp < 2; ntp++) {
            int cn = wn*4 + ntp*2 + sel;
            uint32_t addr = Bb + row*256 + (((uint32_t)(cn ^ rl)) << 4);
            ldm_x4t(bf[2*ntp][0], bf[2*ntp+1][0], bf[2*ntp][1], bf[2*ntp+1][1], addr);
        }
    } else {
        int half = (lane >> 3) & 1, kc = lane >> 4;
        #pragma unroll
        for (int ntp = 0; ntp < 2; ntp++) {
            int row = wn*32 + ntp*16 + half*8 + rl;
            uint32_t addr = Bb + row*128 + ((((ks << 1) | kc) ^ rl) << 4);
            ldm_x4(bf[2*ntp][0], bf[2*ntp+1][0], bf[2*ntp][1], bf[2*ntp+1][1], addr);
        }
    }
}
template<int AL, int BL, int NCH, int MT>
__device__ __forceinline__ void mma_core_3s(const __half* __restrict__ Ag, int lda,
                                            const __half* __restrict__ Bg, int ldb,
                                            float acc[2][4][4], char* smraw) {
    const int tid = threadIdx.x, lane = tid & 31;
    const int wid = tid >> 5, wm = wid & 3, wn = wid >> 2;
    constexpr uint32_t ABYTES = MT*8192u;
    constexpr uint32_t STGB   = ABYTES + 16384u;
    const uint32_t sb = smem_u32(smraw);

    cpA3<AL,MT>(sb, Ag, lda, 0, tid);
    cpB3<BL>(sb + ABYTES, Bg, ldb, 0, tid);
    CP_COMMIT();
    if (NCH > 1) {
        cpA3<AL,MT>(sb + STGB, Ag, lda, 64, tid);
        cpB3<BL>(sb + STGB + ABYTES, Bg, ldb, 64, tid);
    }
    CP_COMMIT();

    uint32_t af[2][4], bf[4][2];
    int cur = 0, nxt2 = 2;
    #pragma unroll 1
    for (int c = 0; c < NCH; c++) {
        CP_WAIT1();
        __syncthreads();
        if (c + 2 < NCH) {
            uint32_t ns = sb + (uint32_t)nxt2*STGB;
            cpA3<AL,MT>(ns, Ag, lda, (c+2)*64, tid);
            cpB3<BL>(ns + ABYTES, Bg, ldb, (c+2)*64, tid);
        }
        CP_COMMIT();
        uint32_t Ab = sb + (uint32_t)cur*STGB;
        uint32_t Bb = Ab + ABYTES;
        #pragma unroll
        for (int ks = 0; ks < 4; ks++) {
            ldfA3<AL,MT>(Ab, ks, wm, lane, af);
            ldfB3<BL>(Bb, ks, wn, lane, bf);
            mma_step(acc, af, bf, MT);
        }
        cur++;  if (cur == 3) cur = 0;
        nxt2++; if (nxt2 == 3) nxt2 = 0;
    }
    __syncthreads();
}

#define SMEM_3S2  98304   // MT=2: 3 * 32KB
#define SMEM_3S1  73728   // MT=1: 3 * 24KB

// epilogue index helpers
#define ROW128(mt, h)  (wm*32 + (mt)*16 + group + 8*(h))
#define ROW64(h)       (wm*16 + group + 8*(h))
#define COL_OF(nt)     (wn*32 + (nt)*8 + 2*tg)

// ---------------- input conversion fp32 -> fp16 ----------------
__global__ void k_half(const float* __restrict__ seq, const float* __restrict__ wk,
                       const float* __restrict__ wv,  const float* __restrict__ wq,
                       const float* __restrict__ w1,  const float* __restrict__ w2) {
    int i4 = blockIdx.x*256 + threadIdx.x;
    const float4* src; __half* dst; int off;
    if      (i4 < 524288) { src = (const float4*)seq; dst = g_seqH; off = i4; }
    else if (i4 < 528384) { src = (const float4*)wk;  dst = g_wkH;  off = i4 - 524288; }
    else if (i4 < 532480) { src = (const float4*)wv;  dst = g_wvH;  off = i4 - 528384; }
    else if (i4 < 536576) { src = (const float4*)wq;  dst = g_wqH;  off = i4 - 532480; }
    else if (i4 < 552960) { src = (const float4*)w1;  dst = g_w1H;  off = i4 - 536576; }
    else if (i4 < 569344) { src = (const float4*)w2;  dst = g_w2H;  off = i4 - 552960; }
    else return;
    float4 v = src[off];
    uint2 o;
    o.x = h2pack(v.x, v.y);
    o.y = h2pack(v.z, v.w);
    *reinterpret_cast<uint2*>(dst + off*4) = o;
}

// ---------------- scalar kernels ----------------
__device__ __forceinline__ float bred128(float v){
    __shared__ float wr[4];
    #pragma unroll
    for (int o = 16; o > 0; o >>= 1) v += __shfl_down_sync(0xffffffffu, v, o);
    int tid = threadIdx.x;
    if ((tid & 31) == 0) wr[tid >> 5] = v;
    __syncthreads();
    float r = wr[0] + wr[1] + wr[2] + wr[3];
    __syncthreads();
    return r;
}
__global__ void k_dots(const float* __restrict__ seq,
                       const float* __restrict__ wlr,  const float* __restrict__ blr,
                       const float* __restrict__ wdec, const float* __restrict__ bdec,
                       const float* __restrict__ wmom, const float* __restrict__ bmom) {
    int b = blockIdx.x >> 6, c = blockIdx.x & 63;
    int tid = threadIdx.x;
    float x = seq[((size_t)b*4096 + c*64)*D + tid];
    float s1 = bred128(x*wlr[tid]);
    float s2 = bred128(x*wdec[tid]);
    float s3 = bred128(x*wmom[tid]);
    if (tid == 0) {
        g_lrv [b*NC + c] = sigm(s1 + blr[0]);
        g_keep[b*NC + c] = 1.f - sigm(s2 + bdec[0]);
        g_eta [b*NC + c] = sigm(s3 + bmom[0]);
    }
}
__global__ void k_coef() {
    int b = threadIdx.x;
    if (b >= BATCH) return;
    float Av = 1.f, Bv = 1.f;
    g_coef[b*NC + NC-1] = -g_lrv[b*NC + NC-1]*(2.f/128.f);
    for (int j = NC-2; j >= 0; j--) {
        Bv *= g_keep[b*NC + j+1];
        Av  = Bv + g_eta[b*NC + j+1]*Av;
        g_coef[b*NC + j] = -Av*g_lrv[b*NC + j]*(2.f/128.f);
    }
}

// ---------------- G1: K/V/Q = seq @ W ----------------
__global__ __launch_bounds__(NTHR, 2) void g1_proj() {
    extern __shared__ char smraw[];
    const __half* W = (blockIdx.z == 0) ? g_wkH : (blockIdx.z == 1 ? g_wvH : g_wqH);
    int row0 = blockIdx.x * 128;
    float acc[2][4][4] = {};
    mma_core_3s<0,0,2,2>(g_seqH + (size_t)row0*D, D, W, D, acc, smraw);
    const int tid = threadIdx.x, lane = tid & 31, group = lane >> 2, tg = lane & 3;
    const int wid = tid >> 5, wm = wid & 3, wn = wid >> 2;
    float* Of = (blockIdx.z == 0) ? g_K : (blockIdx.z == 1 ? g_V : g_Q);
    __half* Oh = (blockIdx.z == 0) ? g_KH : (blockIdx.z == 2 ? g_QH : nullptr);
    #pragma unroll
    for (int mt = 0; mt < 2; mt++)
        #pragma unroll
        for (int h = 0; h < 2; h++) {
            int tok = row0 + ROW128(mt, h);
            #pragma unroll
            for (int nt = 0; nt < 4; nt++) {
                int cc = COL_OF(nt);
                float v0 = acc[mt][nt][2*h], v1 = acc[mt][nt][2*h+1];
                *reinterpret_cast<float2*>(Of + (size_t)tok*D + cc) = make_float2(v0, v1);
                if (Oh)
                    *reinterpret_cast<uint32_t*>(Oh + (size_t)tok*D + cc) = h2pack(v0, v1);
            }
        }
}

// ---------------- G2: Z = K @ w1 -> gelu(half), gelu'(half) ----------------
__global__ __launch_bounds__(NTHR, 2) void g2_zgelu() {
    extern __shared__ char smraw[];
    int row0 = blockIdx.x*128, n0 = blockIdx.y*128;
    float acc[2][4][4] = {};
    mma_core_3s<0,0,2,2>(g_KH + (size_t)row0*D, D, g_w1H + n0, HID, acc, smraw);
    const int tid = threadIdx.x, lane = tid & 31, group = lane >> 2, tg = lane & 3;
    const int wid = tid >> 5, wm = wid & 3, wn = wid >> 2;
    #pragma unroll
    for (int mt = 0; mt < 2; mt++)
        #pragma unroll
        for (int h = 0; h < 2; h++) {
            int tok = row0 + ROW128(mt, h);
            size_t base = (size_t)tok*HID + n0;
            #pragma unroll
            for (int nt = 0; nt < 4; nt++) {
                int cc = COL_OF(nt);
                float a0, p0, a1, p1;
                gelu_both(acc[mt][nt][2*h],   a0, p0);
                gelu_both(acc[mt][nt][2*h+1], a1, p1);
                *reinterpret_cast<uint32_t*>(g_AH  + base + cc) = h2pack(a0, a1);
                *reinterpret_cast<uint32_t*>(g_GPH + base + cc) = h2pack(p0, p1);
            }
        }
}

// ---------------- G3: H = A @ w2; rmsnorm bwd (64-row tiles) ----------------
__global__ __launch_bounds__(NTHR, 2) void g3_hback(const float* __restrict__ gamma) {
    extern __shared__ char smraw[];
    __shared__ float gam[128];
    const int tid = threadIdx.x;
    if (tid < 128) gam[tid] = gamma[tid];
    int row0 = blockIdx.x * 64;
    float acc[2][4][4] = {};
    mma_core_3s<0,0,8,1>(g_AH + (size_t)row0*HID, HID, g_w2H, D, acc, smraw);
    const int lane = tid & 31, group = lane >> 2, tg = lane & 3;
    const int wid = tid >> 5, wm = wid & 3, wn = wid >> 2;
    float* rs = reinterpret_cast<float*>(smraw);        // [4][64]
    float* cs = reinterpret_cast<float*>(smraw) + 256;  // [4][128]

    #pragma unroll
    for (int h = 0; h < 2; h++) {
        float s = 0;
        #pragma unroll
        for (int nt = 0; nt < 4; nt++)
            s += acc[0][nt][2*h]*acc[0][nt][2*h] + acc[0][nt][2*h+1]*acc[0][nt][2*h+1];
        s += __shfl_xor_sync(0xffffffffu, s, 1);
        s += __shfl_xor_sync(0xffffffffu, s, 2);
        if (tg == 0) rs[wn*64 + ROW64(h)] = s;
    }
    __syncthreads();
    float ir[2], cf[2];
    #pragma unroll
    for (int h = 0; h < 2; h++) {
        int r = ROW64(h);
        float s = rs[r] + rs[64 + r] + rs[128 + r] + rs[192 + r];
        ir[h] = rsqrtf(s*(1.f/128.f) + 1e-6f);
        int tok = row0 + r;
        cf[h] = g_coef[(tok >> 12)*NC + ((tok & 4095) >> 6)];
    }
    __syncthreads();

    #pragma unroll
    for (int h = 0; h < 2; h++) {
        int r = ROW64(h), tok = row0 + r;
        float irr = ir[h], cfv = cf[h];
        float dsum = 0;
        #pragma unroll
        for (int nt = 0; nt < 4; nt++) {
            int cc = COL_OF(nt);
            float2 kk = *reinterpret_cast<const float2*>(g_K + (size_t)tok*D + cc);
            float2 vv = *reinterpret_cast<const float2*>(g_V + (size_t)tok*D + cc);
            float hn0 = acc[0][nt][2*h]*irr,   hn1 = acc[0][nt][2*h+1]*irr;
            float dp0 = cfv*(hn0*gam[cc] + kk.x - vv.x);
            float dp1 = cfv*(hn1*gam[cc+1] + kk.y - vv.y);
            dsum += dp0*gam[cc]*hn0 + dp1*gam[cc+1]*hn1;
        }
        dsum += __shfl_xor_sync(0xffffffffu, dsum, 1);
        dsum += __shfl_xor_sync(0xffffffffu, dsum, 2);
        if (tg == 0) rs[wn*64 + r] = dsum;
    }
    __syncthreads();

    float colp[4][2] = {};
    #pragma unroll
    for (int h = 0; h < 2; h++) {
        int r = ROW64(h), tok = row0 + r;
        float irr = ir[h], cfv = cf[h];
        float rd = (rs[r] + rs[64 + r] + rs[128 + r] + rs[192 + r])*(1.f/128.f);
        #pragma unroll
        for (int nt = 0; nt < 4; nt++) {
            int cc = COL_OF(nt);
            float2 kk = *reinterpret_cast<const float2*>(g_K + (size_t)tok*D + cc);
            float2 vv = *reinterpret_cast<const float2*>(g_V + (size_t)tok*D + cc);
            float hn0 = acc[0][nt][2*h]*irr,   hn1 = acc[0][nt][2*h+1]*irr;
            float dp0 = cfv*(hn0*gam[cc] + kk.x - vv.x);
            float dp1 = cfv*(hn1*gam[cc+1] + kk.y - vv.y);
            float o0 = irr*(dp0*gam[cc]   - hn0*rd);
            float o1 = irr*(dp1*gam[cc+1] - hn1*rd);
            *reinterpret_cast<uint32_t*>(g_dHH + (size_t)tok*D + cc) = h2pack(o0, o1);
            colp[nt][0] += dp0*hn0;
            colp[nt][1] += dp1*hn1;
        }
    }
    __syncthreads();
    #pragma unroll
    for (int nt = 0; nt < 4; nt++)
        #pragma unroll
        for (int j = 0; j < 2; j++) {
            float v = colp[nt][j];
            v += __shfl_xor_sync(0xffffffffu, v, 4);
            v += __shfl_xor_sync(0xffffffffu, v, 8);
            v += __shfl_xor_sync(0xffffffffu, v, 16);
            if (group == 0) cs[wm*128 + COL_OF(nt) + j] = v;
        }
    __syncthreads();
    const int t = threadIdx.x;
    if (t < 128) {
        float s = cs[t] + cs[128 + t] + cs[256 + t] + cs[384 + t];
        g_gfp[blockIdx.x*128 + t] = s;
    }
}

// ---------------- G4: dZ = (dH @ w2^T) * GP ----------------
__global__ __launch_bounds__(NTHR, 2) void g4_da() {
    extern __shared__ char smraw[];
    int row0 = blockIdx.x*128, n0 = blockIdx.y*128;
    float acc[2][4][4] = {};
    mma_core_3s<0,1,2,2>(g_dHH + (size_t)row0*D, D, g_w2H + (size_t)n0*D, D, acc, smraw);
    const int tid = threadIdx.x, lane = tid & 31, group = lane >> 2, tg = lane & 3;
    const int wid = tid >> 5, wm = wid & 3, wn = wid >> 2;
    #pragma unroll
    for (int mt = 0; mt < 2; mt++)
        #pragma unroll
        for (int h = 0; h < 2; h++) {
            int tok = row0 + ROW128(mt, h);
            size_t base = (size_t)tok*HID + n0;
            #pragma unroll
            for (int nt = 0; nt < 4; nt++) {
                int cc = COL_OF(nt);
                float2 gp = __half22float2(
                    *reinterpret_cast<const __half2*>(g_GPH + base + cc));
                *reinterpret_cast<uint32_t*>(g_dZH + base + cc) =
                    h2pack(acc[mt][nt][2*h]*gp.x, acc[mt][nt][2*h+1]*gp.y);
            }
        }
}

// ---------------- G5 merged: y=0 w1p = K^T@dZ ; y=1 w2p = A^T@dH ----------------
__global__ __launch_bounds__(NTHR, 2) void g5_wp() {
    extern __shared__ char smraw[];
    int z = blockIdx.z, bh = z >> 3, sl = z & 7;
    int t0 = bh*4096 + sl*512;
    const __half* Ag; const __half* Bg; int lda, ldb;
    if (blockIdx.y == 0) {
        Ag = g_KH + (size_t)t0*D;                     lda = D;
        Bg = g_dZH + (size_t)t0*HID + blockIdx.x*128; ldb = HID;
    } else {
        Ag = g_AH + (size_t)t0*HID + blockIdx.x*128;  lda = HID;
        Bg = g_dHH + (size_t)t0*D;                    ldb = D;
    }
    float acc[2][4][4] = {};
    mma_core_3s<1,0,8,2>(Ag, lda, Bg, ldb, acc, smraw);
    const int tid = threadIdx.x, lane = tid & 31, group = lane >> 2, tg = lane & 3;
    const int wid = tid >> 5, wm = wid & 3, wn = wid >> 2;
    if (blockIdx.y == 0) {
        float* C = g_w1p + (size_t)z*(D*HID);
        int n0 = blockIdx.x * 128;
        #pragma unroll
        for (int mt = 0; mt < 2; mt++)
            #pragma unroll
            for (int h = 0; h < 2; h++) {
                int r = ROW128(mt, h);
                #pragma unroll
                for (int nt = 0; nt < 4; nt++)
                    *reinterpret_cast<float2*>(C + (size_t)r*HID + n0 + COL_OF(nt)) =
                        make_float2(acc[mt][nt][2*h], acc[mt][nt][2*h+1]);
            }
    } else {
        float* C = g_w2p + (size_t)z*(HID*D);
        int m0 = blockIdx.x * 128;
        #pragma unroll
        for (int mt = 0; mt < 2; mt++)
            #pragma unroll
            for (int h = 0; h < 2; h++) {
                int r = m0 + ROW128(mt, h);
                #pragma unroll
                for (int nt = 0; nt < 4; nt++)
                    *reinterpret_cast<float2*>(C + (size_t)r*D + COL_OF(nt)) =
                        make_float2(acc[mt][nt][2*h], acc[mt][nt][2*h+1]);
            }
    }
}

// ---------------- reduce split-K partials -> half finals + dgamma --------------
__global__ void k_reduce() {
    int i = blockIdx.x*256 + threadIdx.x;
    if (i < BATCH*D*HID) {
        int bh = i >> 16, off = i & 65535;
        float s1 = 0, s2 = 0;
        #pragma unroll
        for (int s = 0; s < SLICES; s++) {
            s1 += g_w1p[(size_t)(bh*SLICES + s)*(D*HID) + off];
            s2 += g_w2p[(size_t)(bh*SLICES + s)*(HID*D) + off];
        }
        g_w1fH[i] = __float2half_rn(s1);
        g_w2fH[i] = __float2half_rn(s2);
    }
    if (i < BATCH*D) {
        int bh = i >> 7, col = i & 127;
        float s = 0;
        #pragma unroll
        for (int q = 0; q < 64; q++) s += g_gfp[(bh*64 + q)*128 + col];
        g_gf[i] = s;
    }
}

// ---------------- G6: A2 = gelu(Q @ w1f) ----------------
__global__ __launch_bounds__(NTHR, 2) void g6_z2() {
    extern __shared__ char smraw[];
    int row0 = blockIdx.x*128, n0 = blockIdx.y*128;
    int bh = row0 >> 12;
    float acc[2][4][4] = {};
    mma_core_3s<0,0,2,2>(g_QH + (size_t)row0*D, D,
                         g_w1fH + (size_t)bh*(D*HID) + n0, HID, acc, smraw);
    const int tid = threadIdx.x, lane = tid & 31, group = lane >> 2, tg = lane & 3;
    const int wid = tid >> 5, wm = wid & 3, wn = wid >> 2;
    #pragma unroll
    for (int mt = 0; mt < 2; mt++)
        #pragma unroll
        for (int h = 0; h < 2; h++) {
            int tok = row0 + ROW128(mt, h);
            size_t base = (size_t)tok*HID + n0;
            #pragma unroll
            for (int nt = 0; nt < 4; nt++) {
                int cc = COL_OF(nt);
                *reinterpret_cast<uint32_t*>(g_A2H + base + cc) =
                    h2pack(gelu_f(acc[mt][nt][2*h]), gelu_f(acc[mt][nt][2*h+1]));
            }
        }
}

// ---------------- G7: out = rmsnorm(A2 @ w2f)*gf + Q (64-row tiles) -------------
__global__ __launch_bounds__(NTHR, 2) void g7_out(float* __restrict__ out) {
    extern __shared__ char smraw[];
    __shared__ float gfs[128];
    const int tid = threadIdx.x;
    int row0 = blockIdx.x * 64;
    int bh = row0 >> 12;
    if (tid < 128) gfs[tid] = g_gf[bh*D + tid];
    float acc[2][4][4] = {};
    mma_core_3s<0,0,8,1>(g_A2H + (size_t)row0*HID, HID,
                         g_w2fH + (size_t)bh*(HID*D), D, acc, smraw);
    const int lane = tid & 31, group = lane >> 2, tg = lane & 3;
    const int wid = tid >> 5, wm = wid & 3, wn = wid >> 2;
    float* rs = reinterpret_cast<float*>(smraw);  // [4][64]
    #pragma unroll
    for (int h = 0; h < 2; h++) {
        float s = 0;
        #pragma unroll
        for (int nt = 0; nt < 4; nt++)
            s += acc[0][nt][2*h]*acc[0][nt][2*h] + acc[0][nt][2*h+1]*acc[0][nt][2*h+1];
        s += __shfl_xor_sync(0xffffffffu, s, 1);
        s += __shfl_xor_sync(0xffffffffu, s, 2);
        if (tg == 0) rs[wn*64 + ROW64(h)] = s;
    }
    __syncthreads();
    #pragma unroll
    for (int h = 0; h < 2; h++) {
        int r = ROW64(h), tok = row0 + r;
        float s = rs[r] + rs[64 + r] + rs[128 + r] + rs[192 + r];
        float irr = rsqrtf(s*(1.f/128.f) + 1e-6f);
        #pragma unroll
        for (int nt = 0; nt < 4; nt++) {
            int cc = COL_OF(nt);
            float2 qq = *reinterpret_cast<const float2*>(g_Q + (size_t)tok*D + cc);
            *reinterpret_cast<float2*>(out + (size_t)tok*D + cc) =
                make_float2(acc[0][nt][2*h]*irr*gfs[cc] + qq.x,
                            acc[0][nt][2*h+1]*irr*gfs[cc+1] + qq.y);
        }
    }
}

// ---------------- launch ----------------
extern "C" void kernel_launch(void* const* d_in, const int* in_sizes, int n_in,
                              void* d_out, int out_size) {
    (void)in_sizes; (void)n_in; (void)out_size;
    const float* seq  = (const float*)d_in[0];
    const float* wk   = (const float*)d_in[1];
    const float* wv   = (const float*)d_in[2];
    const float* wq   = (const float*)d_in[3];
    const float* wlr  = (const float*)d_in[4];
    const float* blr  = (const float*)d_in[5];
    const float* wdec = (const float*)d_in[6];
    const float* bdec = (const float*)d_in[7];
    const float* wmom = (const float*)d_in[8];
    const float* bmom = (const float*)d_in[9];
    const float* gamma= (const float*)d_in[10];
    const float* w1   = (const float*)d_in[11];
    const float* w2   = (const float*)d_in[12];
    float* out = (float*)d_out;

    cudaFuncSetAttribute(g1_proj,  cudaFuncAttributeMaxDynamicSharedMemorySize, SMEM_3S2);
    cudaFuncSetAttribute(g2_zgelu, cudaFuncAttributeMaxDynamicSharedMemorySize, SMEM_3S2);
    cudaFuncSetAttribute(g3_hback, cudaFuncAttributeMaxDynamicSharedMemorySize, SMEM_3S1);
    cudaFuncSetAttribute(g4_da,    cudaFuncAttributeMaxDynamicSharedMemorySize, SMEM_3S2);
    cudaFuncSetAttribute(g5_wp,    cudaFuncAttributeMaxDynamicSharedMemorySize, SMEM_3S2);
    cudaFuncSetAttribute(g6_z2,    cudaFuncAttributeMaxDynamicSharedMemorySize, SMEM_3S2);
    cudaFuncSetAttribute(g7_out,   cudaFuncAttributeMaxDynamicSharedMemorySize, SMEM_3S1);

    k_half  <<<2224, 256>>>(seq, wk, wv, wq, w1, w2);
    k_dots  <<<BATCH*NC, 128>>>(seq, wlr, blr, wdec, bdec, wmom, bmom);
    k_coef  <<<1, 32>>>();
    g1_proj <<<dim3(NTOK/128, 1, 3), NTHR, SMEM_3S2>>>();
    g2_zgelu<<<dim3(NTOK/128, HID/128), NTHR, SMEM_3S2>>>();
    g3_hback<<<NTOK/64, NTHR, SMEM_3S1>>>(gamma);
    g4_da   <<<dim3(NTOK/128, HID/128), NTHR, SMEM_3S2>>>();
    g5_wp   <<<dim3(HID/128, 2, BATCH*SLICES), NTHR, SMEM_3S2>>>();
    k_reduce<<<(BATCH*D*HID)/256, 256>>>();
    g6_z2   <<<dim3(NTOK/128, HID/128), NTHR, SMEM_3S2>>>();
    g7_out  <<<NTOK/64, NTHR, SMEM_3S1>>>(out);
}

// round 14
// speedup vs baseline: 1.1317x; 1.0891x over previous
#include <cuda_runtime.h>
#include <cuda_fp16.h>
#include <stdint.h>
#include <math.h>

// dims: b=4, n=4096, d=128, hid=512, CHUNK=64
#define NTOK 16384
#define D 128
#define HID 512
#define NC 64
#define BATCH 4
#define SLICES 8
#define NTHR 512

// ---------------- scratch ----------------
__device__ float  g_Q [NTOK*D];      // fp32 residual for g7
__device__ __half g_GPH[NTOK*HID];
__device__ __half g_seqH[NTOK*D];
__device__ __half g_wkH[D*D], g_wvH[D*D], g_wqH[D*D];
__device__ __half g_w1H[D*HID];
__device__ __half g_w2H[HID*D];
__device__ __half g_KH [NTOK*D];
__device__ __half g_VH [NTOK*D];
__device__ __half g_QH [NTOK*D];
__device__ __half g_AH [NTOK*HID];
__device__ __half g_dHH[NTOK*D];
__device__ __half g_dZH[NTOK*HID];
__device__ __half g_A2H[NTOK*HID];
__device__ __half g_w1fH[BATCH*D*HID];
__device__ __half g_w2fH[BATCH*HID*D];
__device__ float  g_lrv [BATCH*NC];
__device__ float  g_keep[BATCH*NC];
__device__ float  g_eta [BATCH*NC];
__device__ float  g_coef[BATCH*NC];
__device__ float  g_gfp[256*D];
__device__ float  g_gf [BATCH*D];
__device__ float  g_w1p[BATCH*SLICES*D*HID];
__device__ float  g_w2p[BATCH*SLICES*HID*D];

// ---------------- helpers ----------------
__device__ __forceinline__ float sigm(float x){ return 1.f/(1.f+expf(-x)); }
__device__ __forceinline__ float tanh_fast(float u){
    float e = __expf(2.f*u);
    return 1.f - __fdividef(2.f, e + 1.f);
}
__device__ __forceinline__ void gelu_both(float x, float& a, float& gp){
    const float c0 = 0.7978845608028654f, c1 = 0.044715f;
    float x2 = x*x;
    float t = tanh_fast(c0*x*(1.f + c1*x2));
    a  = 0.5f*x*(1.f + t);
    gp = 0.5f*(1.f + t) + 0.5f*x*(1.f - t*t)*c0*(1.f + 3.f*c1*x2);
}
__device__ __forceinline__ float gelu_f(float x){
    float t = tanh_fast(0.7978845608028654f*x*(1.f + 0.044715f*x*x));
    return 0.5f*x*(1.f + t);
}
__device__ __forceinline__ uint32_t h2pack(float lo, float hi){
    __half2 h = __floats2half2_rn(lo, hi);
    return *reinterpret_cast<uint32_t*>(&h);
}
__device__ __forceinline__ void mma16(float& c0, float& c1, float& c2, float& c3,
                                      uint32_t a0, uint32_t a1, uint32_t a2, uint32_t a3,
                                      uint32_t b0, uint32_t b1){
    asm volatile("mma.sync.aligned.m16n8k16.row.col.f32.f16.f16.f32 "
                 "{%0,%1,%2,%3}, {%4,%5,%6,%7}, {%8,%9}, {%0,%1,%2,%3};"
                 : "+f"(c0), "+f"(c1), "+f"(c2), "+f"(c3)
                 : "r"(a0), "r"(a1), "r"(a2), "r"(a3), "r"(b0), "r"(b1));
}
__device__ __forceinline__ uint32_t smem_u32(const void* p){
    uint32_t a;
    asm("{ .reg .u64 t; cvta.to.shared.u64 t, %1; cvt.u32.u64 %0, t; }" : "=r"(a) : "l"(p));
    return a;
}
__device__ __forceinline__ void cp16(uint32_t dst, const void* src){
    asm volatile("cp.async.cg.shared.global [%0], [%1], 16;" :: "r"(dst), "l"(src));
}
#define CP_COMMIT() asm volatile("cp.async.commit_group;" ::: "memory")
#define CP_WAIT1()  asm volatile("cp.async.wait_group 1;" ::: "memory")
#define CP_WAIT0()  asm volatile("cp.async.wait_group 0;" ::: "memory")
__device__ __forceinline__ void ldm_x4(uint32_t& r0, uint32_t& r1, uint32_t& r2, uint32_t& r3,
                                       uint32_t a){
    asm volatile("ldmatrix.sync.aligned.m8n8.x4.shared.b16 {%0,%1,%2,%3}, [%4];"
                 : "=r"(r0), "=r"(r1), "=r"(r2), "=r"(r3) : "r"(a));
}
__device__ __forceinline__ void ldm_x4t(uint32_t& r0, uint32_t& r1, uint32_t& r2, uint32_t& r3,
                                        uint32_t a){
    asm volatile("ldmatrix.sync.aligned.m8n8.x4.trans.shared.b16 {%0,%1,%2,%3}, [%4];"
                 : "=r"(r0), "=r"(r1), "=r"(r2), "=r"(r3) : "r"(a));
}
__device__ __forceinline__ void mma_step(float acc[2][4][4],
                                         const uint32_t af[2][4], const uint32_t bf[4][2],
                                         int MTn) {
    #pragma unroll
    for (int nt = 0; nt < 4; nt++)
        #pragma unroll
        for (int mt = 0; mt < 2; mt++)
            if (mt < MTn)
                mma16(acc[mt][nt][0], acc[mt][nt][1], acc[mt][nt][2], acc[mt][nt][3],
                      af[mt][0], af[mt][1], af[mt][2], af[mt][3], bf[nt][0], bf[nt][1]);
}

// ============ 64x128 tile, K=128, 256-thread, 2-stage core (occ 4) ==============
// A gmem [m][k] k-contig (64 rows); smem rows m, 128B/row, XOR swizzle.
// BL=0: B gmem [k][n] n-contig; smem rows k, 256B/row.
// BL=1: B gmem [n][k] k-contig; smem rows n, 128B/row.
// Warp grid: 8 warps = 2(m) x 4(n); warp tile 32x32 (2 mtiles x 4 ntiles m16n8k16).
#define STG64 24576u   // 8KB A + 16KB B
#define SMEM64 49152

__device__ __forceinline__ void cpA64(uint32_t dstb, const __half* __restrict__ Ag, int lda,
                                      int k0, int tid){
    #pragma unroll
    for (int j = 0; j < 2; j++) {
        int i = tid + j*256;
        int m = i >> 3, c = i & 7;
        cp16(dstb + (uint32_t)(m*128 + ((c ^ (m & 7)) << 4)),
             Ag + (size_t)m*lda + k0 + c*8);
    }
}
template<int BL>
__device__ __forceinline__ void cpB64(uint32_t dstb, const __half* __restrict__ Bg, int ldb,
                                      int k0, int tid){
    #pragma unroll
    for (int j = 0; j < 4; j++) {
        int i = tid + j*256;
        if (BL == 0) { int r = i >> 4, c = i & 15;
            cp16(dstb + (uint32_t)(r*256 + ((c ^ (r & 7)) << 4)),
                 Bg + (size_t)(k0 + r)*ldb + c*8); }
        else         { int n = i >> 3, c = i & 7;
            cp16(dstb + (uint32_t)(n*128 + ((c ^ (n & 7)) << 4)),
                 Bg + (size_t)n*ldb + k0 + c*8); }
    }
}
template<int BL>
__device__ __forceinline__ void core64(const __half* __restrict__ Ag, int lda,
                                       const __half* __restrict__ Bg, int ldb,
                                       float acc[2][4][4], char* smraw){
    const int tid = threadIdx.x, lane = tid & 31;
    const int wid = tid >> 5, wm = wid & 1, wn = wid >> 1;
    const uint32_t sb = smem_u32(smraw);

    cpA64(sb, Ag, lda, 0, tid);
    cpB64<BL>(sb + 8192u, Bg, ldb, 0, tid);
    CP_COMMIT();
    cpA64(sb + STG64, Ag, lda, 64, tid);
    cpB64<BL>(sb + STG64 + 8192u, Bg, ldb, 64, tid);
    CP_COMMIT();

    const int rl = lane & 7, half = (lane >> 3) & 1, kc = lane >> 4;
    uint32_t af[2][4], bf[4][2];
    #pragma unroll
    for (int c = 0; c < 2; c++) {
        if (c == 0) CP_WAIT1(); else CP_WAIT0();
        __syncthreads();
        uint32_t Ab = sb + (uint32_t)c*STG64;
        uint32_t Bb = Ab + 8192u;
        #pragma unroll
        for (int ks = 0; ks < 4; ks++) {
            #pragma unroll
            for (int mt = 0; mt < 2; mt++) {
                int row = wm*32 + mt*16 + half*8 + rl;
                uint32_t addr = Ab + row*128 + ((((ks << 1) | kc) ^ rl) << 4);
                ldm_x4(af[mt][0], af[mt][1], af[mt][2], af[mt][3], addr);
            }
            if (BL == 0) {
                int row = 16*ks + 8*kc + rl;
                #pragma unroll
                for (int ntp = 0; ntp < 2; ntp++) {
                    int cn = wn*4 + ntp*2 + half;
                    uint32_t addr = Bb + row*256 + (((uint32_t)(cn ^ rl)) << 4);
                    ldm_x4t(bf[2*ntp][0], bf[2*ntp+1][0], bf[2*ntp][1], bf[2*ntp+1][1], addr);
                }
            } else {
                #pragma unroll
                for (int ntp = 0; ntp < 2; ntp++) {
                    int row = wn*32 + ntp*16 + half*8 + rl;
                    uint32_t addr = Bb + row*128 + ((((ks << 1) | kc) ^ rl) << 4);
                    ldm_x4(bf[2*ntp][0], bf[2*ntp+1][0], bf[2*ntp][1], bf[2*ntp+1][1], addr);
                }
            }
            mma_step(acc, af, bf, 2);
        }
    }
}

// ============ unified 3-stage BK=64 pipelined core (K=512 GEMMs, 512 thr) =======
template<int AL, int MT>
__device__ __forceinline__ void cpA3(uint32_t dstb, const __half* __restrict__ Ag, int lda,
                                     int k0, int tid){
    #pragma unroll
    for (int j = 0; j < MT; j++) {
        int i = tid + j*NTHR;
        if (AL == 0) { int m = i >> 3, c = i & 7;
            cp16(dstb + (uint32_t)(m*128 + ((c ^ (m & 7)) << 4)),
                 Ag + (size_t)m*lda + k0 + c*8); }
        else         { int r = i >> 4, c = i & 15;
            cp16(dstb + (uint32_t)(r*256 + ((c ^ (r & 7)) << 4)),
                 Ag + (size_t)(k0 + r)*lda + c*8); }
    }
}
__device__ __forceinline__ void cpB3(uint32_t dstb, const __half* __restrict__ Bg, int ldb,
                                     int k0, int tid){
    #pragma unroll
    for (int j = 0; j < 2; j++) {
        int i = tid + j*NTHR;
        int r = i >> 4, c = i & 15;
        cp16(dstb + (uint32_t)(r*256 + ((c ^ (r & 7)) << 4)),
             Bg + (size_t)(k0 + r)*ldb + c*8);
    }
}
template<int AL, int MT>
__device__ __forceinline__ void ldfA3(uint32_t Ab, int ks, int wm, int lane,
                                      uint32_t af[2][4]){
    int rl = lane & 7;
    if (AL == 0) {
        int half = (lane >> 3) & 1, kc = lane >> 4;
        #pragma unroll
        for (int mt = 0; mt < MT; mt++) {
            int row = wm*(16*MT) + mt*16 + half*8 + rl;
            uint32_t addr = Ab + row*128 + ((((ks << 1) | kc) ^ rl) << 4);
            ldm_x4(af[mt][0], af[mt][1], af[mt][2], af[mt][3], addr);
        }
    } else {
        int sel = (lane >> 3) & 1, kh = lane >> 4;
        int row = 16*ks + 8*kh + rl;
        #pragma unroll
        for (int mt = 0; mt < MT; mt++) {
            int cm = wm*(2*MT) + mt*2 + sel;
            uint32_t addr = Ab + row*256 + (((uint32_t)(cm ^ rl)) << 4);
            ldm_x4t(af[mt][0], af[mt][1], af[mt][2], af[mt][3], addr);
        }
    }
}
__device__ __forceinline__ void ldfB3(uint32_t Bb, int ks, int wn, int lane,
                                      uint32_t bf[4][2]){
    int rl = lane & 7;
    int sel = (lane >> 3) & 1, kh = lane >> 4;
    int row = 16*ks + 8*kh + rl;
    #pragma unroll
    for (int ntp = 0; ntp < 2; ntp++) {
        int cn = wn*4 + ntp*2 + sel;
        uint32_t addr = Bb + row*256 + (((uint32_t)(cn ^ rl)) << 4);
        ldm_x4t(bf[2*ntp][0], bf[2*ntp+1][0], bf[2*ntp][1], bf[2*ntp+1][1], addr);
    }
}
template<int AL, int NCH, int MT>
__device__ __forceinline__ void mma_core_3s(const __half* __restrict__ Ag, int lda,
                                            const __half* __restrict__ Bg, int ldb,
                                            float acc[2][4][4], char* smraw) {
    const int tid = threadIdx.x, lane = tid & 31;
    const int wid = tid >> 5, wm = wid & 3, wn = wid >> 2;
    constexpr uint32_t ABYTES = MT*8192u;
    constexpr uint32_t STGB   = ABYTES + 16384u;
    const uint32_t sb = smem_u32(smraw);

    cpA3<AL,MT>(sb, Ag, lda, 0, tid);
    cpB3(sb + ABYTES, Bg, ldb, 0, tid);
    CP_COMMIT();
    cpA3<AL,MT>(sb + STGB, Ag, lda, 64, tid);
    cpB3(sb + STGB + ABYTES, Bg, ldb, 64, tid);
    CP_COMMIT();

    uint32_t af[2][4], bf[4][2];
    int cur = 0, nxt2 = 2;
    #pragma unroll 1
    for (int c = 0; c < NCH; c++) {
        CP_WAIT1();
        __syncthreads();
        if (c + 2 < NCH) {
            uint32_t ns = sb + (uint32_t)nxt2*STGB;
            cpA3<AL,MT>(ns, Ag, lda, (c+2)*64, tid);
            cpB3(ns + ABYTES, Bg, ldb, (c+2)*64, tid);
        }
        CP_COMMIT();
        uint32_t Ab = sb + (uint32_t)cur*STGB;
        uint32_t Bb = Ab + ABYTES;
        #pragma unroll
        for (int ks = 0; ks < 4; ks++) {
            ldfA3<AL,MT>(Ab, ks, wm, lane, af);
            ldfB3(Bb, ks, wn, lane, bf);
            mma_step(acc, af, bf, MT);
        }
        cur++;  if (cur == 3) cur = 0;
        nxt2++; if (nxt2 == 3) nxt2 = 0;
    }
    __syncthreads();
}

#define SMEM_3S2  98304
#define SMEM_3S1  73728

// epilogue index helpers
#define ROW64T(mt, h)  (wm*32 + (mt)*16 + group + 8*(h))   // 64-row tiles (wm 0..1)
#define ROW128(mt, h)  (wm*32 + (mt)*16 + group + 8*(h))   // 128-row tiles (wm 0..3)
#define ROW64(h)       (wm*16 + group + 8*(h))
#define COL_OF(nt)     (wn*32 + (nt)*8 + 2*tg)

// ---------------- input conversion fp32 -> fp16 ----------------
__global__ void k_half(const float* __restrict__ seq, const float* __restrict__ wk,
                       const float* __restrict__ wv,  const float* __restrict__ wq,
                       const float* __restrict__ w1,  const float* __restrict__ w2) {
    int i4 = blockIdx.x*256 + threadIdx.x;
    const float4* src; __half* dst; int off;
    if      (i4 < 524288) { src = (const float4*)seq; dst = g_seqH; off = i4; }
    else if (i4 < 528384) { src = (const float4*)wk;  dst = g_wkH;  off = i4 - 524288; }
    else if (i4 < 532480) { src = (const float4*)wv;  dst = g_wvH;  off = i4 - 528384; }
    else if (i4 < 536576) { src = (const float4*)wq;  dst = g_wqH;  off = i4 - 532480; }
    else if (i4 < 552960) { src = (const float4*)w1;  dst = g_w1H;  off = i4 - 536576; }
    else if (i4 < 569344) { src = (const float4*)w2;  dst = g_w2H;  off = i4 - 552960; }
    else return;
    float4 v = src[off];
    uint2 o;
    o.x = h2pack(v.x, v.y);
    o.y = h2pack(v.z, v.w);
    *reinterpret_cast<uint2*>(dst + off*4) = o;
}

// ---------------- scalar kernels ----------------
__device__ __forceinline__ float bred128(float v){
    __shared__ float wr[4];
    #pragma unroll
    for (int o = 16; o > 0; o >>= 1) v += __shfl_down_sync(0xffffffffu, v, o);
    int tid = threadIdx.x;
    if ((tid & 31) == 0) wr[tid >> 5] = v;
    __syncthreads();
    float r = wr[0] + wr[1] + wr[2] + wr[3];
    __syncthreads();
    return r;
}
__global__ void k_dots(const float* __restrict__ seq,
                       const float* __restrict__ wlr,  const float* __restrict__ blr,
                       const float* __restrict__ wdec, const float* __restrict__ bdec,
                       const float* __restrict__ wmom, const float* __restrict__ bmom) {
    int b = blockIdx.x >> 6, c = blockIdx.x & 63;
    int tid = threadIdx.x;
    float x = seq[((size_t)b*4096 + c*64)*D + tid];
    float s1 = bred128(x*wlr[tid]);
    float s2 = bred128(x*wdec[tid]);
    float s3 = bred128(x*wmom[tid]);
    if (tid == 0) {
        g_lrv [b*NC + c] = sigm(s1 + blr[0]);
        g_keep[b*NC + c] = 1.f - sigm(s2 + bdec[0]);
        g_eta [b*NC + c] = sigm(s3 + bmom[0]);
    }
}
__global__ void k_coef() {
    int b = threadIdx.x;
    if (b >= BATCH) return;
    float Av = 1.f, Bv = 1.f;
    g_coef[b*NC + NC-1] = -g_lrv[b*NC + NC-1]*(2.f/128.f);
    for (int j = NC-2; j >= 0; j--) {
        Bv *= g_keep[b*NC + j+1];
        Av  = Bv + g_eta[b*NC + j+1]*Av;
        g_coef[b*NC + j] = -Av*g_lrv[b*NC + j]*(2.f/128.f);
    }
}

// ---------------- G1: K/V/Q = seq @ W  (64-row, occ4) ----------------
__global__ __launch_bounds__(256, 4) void g1_proj() {
    extern __shared__ char smraw[];
    const __half* W = (blockIdx.z == 0) ? g_wkH : (blockIdx.z == 1 ? g_wvH : g_wqH);
    int row0 = blockIdx.x * 64;
    float acc[2][4][4] = {};
    core64<0>(g_seqH + (size_t)row0*D, D, W, D, acc, smraw);
    const int tid = threadIdx.x, lane = tid & 31, group = lane >> 2, tg = lane & 3;
    const int wid = tid >> 5, wm = wid & 1, wn = wid >> 1;
    __half* Oh = (blockIdx.z == 0) ? g_KH : (blockIdx.z == 1 ? g_VH : g_QH);
    bool wq32 = (blockIdx.z == 2);
    #pragma unroll
    for (int mt = 0; mt < 2; mt++)
        #pragma unroll
        for (int h = 0; h < 2; h++) {
            int tok = row0 + ROW64T(mt, h);
            #pragma unroll
            for (int nt = 0; nt < 4; nt++) {
                int cc = COL_OF(nt);
                float v0 = acc[mt][nt][2*h], v1 = acc[mt][nt][2*h+1];
                *reinterpret_cast<uint32_t*>(Oh + (size_t)tok*D + cc) = h2pack(v0, v1);
                if (wq32)
                    *reinterpret_cast<float2*>(g_Q + (size_t)tok*D + cc) = make_float2(v0, v1);
            }
        }
}

// ---------------- G2: Z = K @ w1 -> gelu (64-row, occ4) ----------------
__global__ __launch_bounds__(256, 4) void g2_zgelu() {
    extern __shared__ char smraw[];
    int row0 = blockIdx.x*64, n0 = blockIdx.y*128;
    float acc[2][4][4] = {};
    core64<0>(g_KH + (size_t)row0*D, D, g_w1H + n0, HID, acc, smraw);
    const int tid = threadIdx.x, lane = tid & 31, group = lane >> 2, tg = lane & 3;
    const int wid = tid >> 5, wm = wid & 1, wn = wid >> 1;
    #pragma unroll
    for (int mt = 0; mt < 2; mt++)
        #pragma unroll
        for (int h = 0; h < 2; h++) {
            int tok = row0 + ROW64T(mt, h);
            size_t base = (size_t)tok*HID + n0;
            #pragma unroll
            for (int nt = 0; nt < 4; nt++) {
                int cc = COL_OF(nt);
                float a0, p0, a1, p1;
                gelu_both(acc[mt][nt][2*h],   a0, p0);
                gelu_both(acc[mt][nt][2*h+1], a1, p1);
                *reinterpret_cast<uint32_t*>(g_AH  + base + cc) = h2pack(a0, a1);
                *reinterpret_cast<uint32_t*>(g_GPH + base + cc) = h2pack(p0, p1);
            }
        }
}

// ---------------- G3: H = A @ w2; rmsnorm bwd (64-row, 512 thr) -----------------
__global__ __launch_bounds__(NTHR, 2) void g3_hback(const float* __restrict__ gamma) {
    extern __shared__ char smraw[];
    __shared__ float gam[128];
    const int tid = threadIdx.x;
    if (tid < 128) gam[tid] = gamma[tid];
    int row0 = blockIdx.x * 64;
    float acc[2][4][4] = {};
    mma_core_3s<0,8,1>(g_AH + (size_t)row0*HID, HID, g_w2H, D, acc, smraw);
    const int lane = tid & 31, group = lane >> 2, tg = lane & 3;
    const int wid = tid >> 5, wm = wid & 3, wn = wid >> 2;
    float* rs = reinterpret_cast<float*>(smraw);        // [4][64]
    float* cs = reinterpret_cast<float*>(smraw) + 256;  // [4][128]

    #pragma unroll
    for (int h = 0; h < 2; h++) {
        float s = 0;
        #pragma unroll
        for (int nt = 0; nt < 4; nt++)
            s += acc[0][nt][2*h]*acc[0][nt][2*h] + acc[0][nt][2*h+1]*acc[0][nt][2*h+1];
        s += __shfl_xor_sync(0xffffffffu, s, 1);
        s += __shfl_xor_sync(0xffffffffu, s, 2);
        if (tg == 0) rs[wn*64 + ROW64(h)] = s;
    }
    __syncthreads();
    float ir[2], cf[2];
    #pragma unroll
    for (int h = 0; h < 2; h++) {
        int r = ROW64(h);
        float s = rs[r] + rs[64 + r] + rs[128 + r] + rs[192 + r];
        ir[h] = rsqrtf(s*(1.f/128.f) + 1e-6f);
        int tok = row0 + r;
        cf[h] = g_coef[(tok >> 12)*NC + ((tok & 4095) >> 6)];
    }
    __syncthreads();

    #pragma unroll
    for (int h = 0; h < 2; h++) {
        int r = ROW64(h), tok = row0 + r;
        float irr = ir[h], cfv = cf[h];
        float dsum = 0;
        #pragma unroll
        for (int nt = 0; nt < 4; nt++) {
            int cc = COL_OF(nt);
            float2 kk = __half22float2(*reinterpret_cast<const __half2*>(g_KH + (size_t)tok*D + cc));
            float2 vv = __half22float2(*reinterpret_cast<const __half2*>(g_VH + (size_t)tok*D + cc));
            float hn0 = acc[0][nt][2*h]*irr,   hn1 = acc[0][nt][2*h+1]*irr;
            float dp0 = cfv*(hn0*gam[cc] + kk.x - vv.x);
            float dp1 = cfv*(hn1*gam[cc+1] + kk.y - vv.y);
            dsum += dp0*gam[cc]*hn0 + dp1*gam[cc+1]*hn1;
        }
        dsum += __shfl_xor_sync(0xffffffffu, dsum, 1);
        dsum += __shfl_xor_sync(0xffffffffu, dsum, 2);
        if (tg == 0) rs[wn*64 + r] = dsum;
    }
    __syncthreads();

    float colp[4][2] = {};
    #pragma unroll
    for (int h = 0; h < 2; h++) {
        int r = ROW64(h), tok = row0 + r;
        float irr = ir[h], cfv = cf[h];
        float rd = (rs[r] + rs[64 + r] + rs[128 + r] + rs[192 + r])*(1.f/128.f);
        #pragma unroll
        for (int nt = 0; nt < 4; nt++) {
            int cc = COL_OF(nt);
            float2 kk = __half22float2(*reinterpret_cast<const __half2*>(g_KH + (size_t)tok*D + cc));
            float2 vv = __half22float2(*reinterpret_cast<const __half2*>(g_VH + (size_t)tok*D + cc));
            float hn0 = acc[0][nt][2*h]*irr,   hn1 = acc[0][nt][2*h+1]*irr;
            float dp0 = cfv*(hn0*gam[cc] + kk.x - vv.x);
            float dp1 = cfv*(hn1*gam[cc+1] + kk.y - vv.y);
            float o0 = irr*(dp0*gam[cc]   - hn0*rd);
            float o1 = irr*(dp1*gam[cc+1] - hn1*rd);
            *reinterpret_cast<uint32_t*>(g_dHH + (size_t)tok*D + cc) = h2pack(o0, o1);
            colp[nt][0] += dp0*hn0;
            colp[nt][1] += dp1*hn1;
        }
    }
    __syncthreads();
    #pragma unroll
    for (int nt = 0; nt < 4; nt++)
        #pragma unroll
        for (int j = 0; j < 2; j++) {
            float v = colp[nt][j];
            v += __shfl_xor_sync(0xffffffffu, v, 4);
            v += __shfl_xor_sync(0xffffffffu, v, 8);
            v += __shfl_xor_sync(0xffffffffu, v, 16);
            if (group == 0) cs[wm*128 + COL_OF(nt) + j] = v;
        }
    __syncthreads();
    const int t = threadIdx.x;
    if (t < 128) {
        float s = cs[t] + cs[128 + t] + cs[256 + t] + cs[384 + t];
        g_gfp[blockIdx.x*128 + t] = s;
    }
}

// ---------------- G4: dZ = (dH @ w2^T) * GP (64-row, occ4) ----------------
__global__ __launch_bounds__(256, 4) void g4_da() {
    extern __shared__ char smraw[];
    int row0 = blockIdx.x*64, n0 = blockIdx.y*128;
    float acc[2][4][4] = {};
    core64<1>(g_dHH + (size_t)row0*D, D, g_w2H + (size_t)n0*D, D, acc, smraw);
    const int tid = threadIdx.x, lane = tid & 31, group = lane >> 2, tg = lane & 3;
    const int wid = tid >> 5, wm = wid & 1, wn = wid >> 1;
    #pragma unroll
    for (int mt = 0; mt < 2; mt++)
        #pragma unroll
        for (int h = 0; h < 2; h++) {
            int tok = row0 + ROW64T(mt, h);
            size_t base = (size_t)tok*HID + n0;
            #pragma unroll
            for (int nt = 0; nt < 4; nt++) {
                int cc = COL_OF(nt);
                float2 gp = __half22float2(
                    *reinterpret_cast<const __half2*>(g_GPH + base + cc));
                *reinterpret_cast<uint32_t*>(g_dZH + base + cc) =
                    h2pack(acc[mt][nt][2*h]*gp.x, acc[mt][nt][2*h+1]*gp.y);
            }
        }
}

// ---------------- G5 merged: y=0 w1p = K^T@dZ ; y=1 w2p = A^T@dH ----------------
__global__ __launch_bounds__(NTHR, 2) void g5_wp() {
    extern __shared__ char smraw[];
    int z = blockIdx.z, bh = z >> 3, sl = z & 7;
    int t0 = bh*4096 + sl*512;
    const __half* Ag; const __half* Bg; int lda, ldb;
    if (blockIdx.y == 0) {
        Ag = g_KH + (size_t)t0*D;                     lda = D;
        Bg = g_dZH + (size_t)t0*HID + blockIdx.x*128; ldb = HID;
    } else {
        Ag = g_AH + (size_t)t0*HID + blockIdx.x*128;  lda = HID;
        Bg = g_dHH + (size_t)t0*D;                    ldb = D;
    }
    float acc[2][4][4] = {};
    mma_core_3s<1,8,2>(Ag, lda, Bg, ldb, acc, smraw);
    const int tid = threadIdx.x, lane = tid & 31, group = lane >> 2, tg = lane & 3;
    const int wid = tid >> 5, wm = wid & 3, wn = wid >> 2;
    if (blockIdx.y == 0) {
        float* C = g_w1p + (size_t)z*(D*HID);
        int n0 = blockIdx.x * 128;
        #pragma unroll
        for (int mt = 0; mt < 2; mt++)
            #pragma unroll
            for (int h = 0; h < 2; h++) {
                int r = ROW128(mt, h);
                #pragma unroll
                for (int nt = 0; nt < 4; nt++)
                    *reinterpret_cast<float2*>(C + (size_t)r*HID + n0 + COL_OF(nt)) =
                        make_float2(acc[mt][nt][2*h], acc[mt][nt][2*h+1]);
            }
    } else {
        float* C = g_w2p + (size_t)z*(HID*D);
        int m0 = blockIdx.x * 128;
        #pragma unroll
        for (int mt = 0; mt < 2; mt++)
            #pragma unroll
            for (int h = 0; h < 2; h++) {
                int r = m0 + ROW128(mt, h);
                #pragma unroll
                for (int nt = 0; nt < 4; nt++)
                    *reinterpret_cast<float2*>(C + (size_t)r*D + COL_OF(nt)) =
                        make_float2(acc[mt][nt][2*h], acc[mt][nt][2*h+1]);
            }
    }
}

// ---------------- reduce split-K partials -> half finals + dgamma --------------
__global__ void k_reduce() {
    int i = blockIdx.x*256 + threadIdx.x;
    if (i < BATCH*D*HID) {
        int bh = i >> 16, off = i & 65535;
        float s1 = 0, s2 = 0;
        #pragma unroll
        for (int s = 0; s < SLICES; s++) {
            s1 += g_w1p[(size_t)(bh*SLICES + s)*(D*HID) + off];
            s2 += g_w2p[(size_t)(bh*SLICES + s)*(HID*D) + off];
        }
        g_w1fH[i] = __float2half_rn(s1);
        g_w2fH[i] = __float2half_rn(s2);
    }
    if (i < BATCH*D) {
        int bh = i >> 7, col = i & 127;
        float s = 0;
        #pragma unroll
        for (int q = 0; q < 64; q++) s += g_gfp[(bh*64 + q)*128 + col];
        g_gf[i] = s;
    }
}

// ---------------- G6: A2 = gelu(Q @ w1f) (64-row, occ4) ----------------
__global__ __launch_bounds__(256, 4) void g6_z2() {
    extern __shared__ char smraw[];
    int row0 = blockIdx.x*64, n0 = blockIdx.y*128;
    int bh = row0 >> 12;
    float acc[2][4][4] = {};
    core64<0>(g_QH + (size_t)row0*D, D, g_w1fH + (size_t)bh*(D*HID) + n0, HID, acc, smraw);
    const int tid = threadIdx.x, lane = tid & 31, group = lane >> 2, tg = lane & 3;
    const int wid = tid >> 5, wm = wid & 1, wn = wid >> 1;
    #pragma unroll
    for (int mt = 0; mt < 2; mt++)
        #pragma unroll
        for (int h = 0; h < 2; h++) {
            int tok = row0 + ROW64T(mt, h);
            size_t base = (size_t)tok*HID + n0;
            #pragma unroll
            for (int nt = 0; nt < 4; nt++) {
                int cc = COL_OF(nt);
                *reinterpret_cast<uint32_t*>(g_A2H + base + cc) =
                    h2pack(gelu_f(acc[mt][nt][2*h]), gelu_f(acc[mt][nt][2*h+1]));
            }
        }
}

// ---------------- G7: out = rmsnorm(A2 @ w2f)*gf + Q (64-row, 512 thr) ----------
__global__ __launch_bounds__(NTHR, 2) void g7_out(float* __restrict__ out) {
    extern __shared__ char smraw[];
    __shared__ float gfs[128];
    const int tid = threadIdx.x;
    int row0 = blockIdx.x * 64;
    int bh = row0 >> 12;
    if (tid < 128) gfs[tid] = g_gf[bh*D + tid];
    float acc[2][4][4] = {};
    mma_core_3s<0,8,1>(g_A2H + (size_t)row0*HID, HID,
                       g_w2fH + (size_t)bh*(HID*D), D, acc, smraw);
    const int lane = tid & 31, group = lane >> 2, tg = lane & 3;
    const int wid = tid >> 5, wm = wid & 3, wn = wid >> 2;
    float* rs = reinterpret_cast<float*>(smraw);  // [4][64]
    #pragma unroll
    for (int h = 0; h < 2; h++) {
        float s = 0;
        #pragma unroll
        for (int nt = 0; nt < 4; nt++)
            s += acc[0][nt][2*h]*acc[0][nt][2*h] + acc[0][nt][2*h+1]*acc[0][nt][2*h+1];
        s += __shfl_xor_sync(0xffffffffu, s, 1);
        s += __shfl_xor_sync(0xffffffffu, s, 2);
        if (tg == 0) rs[wn*64 + ROW64(h)] = s;
    }
    __syncthreads();
    #pragma unroll
    for (int h = 0; h < 2; h++) {
        int r = ROW64(h), tok = row0 + r;
        float s = rs[r] + rs[64 + r] + rs[128 + r] + rs[192 + r];
        float irr = rsqrtf(s*(1.f/128.f) + 1e-6f);
        #pragma unroll
        for (int nt = 0; nt < 4; nt++) {
            int cc = COL_OF(nt);
            float2 qq = *reinterpret_cast<const float2*>(g_Q + (size_t)tok*D + cc);
            *reinterpret_cast<float2*>(out + (size_t)tok*D + cc) =
                make_float2(acc[0][nt][2*h]*irr*gfs[cc] + qq.x,
                            acc[0][nt][2*h+1]*irr*gfs[cc+1] + qq.y);
        }
    }
}

// ---------------- launch ----------------
extern "C" void kernel_launch(void* const* d_in, const int* in_sizes, int n_in,
                              void* d_out, int out_size) {
    (void)in_sizes; (void)n_in; (void)out_size;
    const float* seq  = (const float*)d_in[0];
    const float* wk   = (const float*)d_in[1];
    const float* wv   = (const float*)d_in[2];
    const float* wq   = (const float*)d_in[3];
    const float* wlr  = (const float*)d_in[4];
    const float* blr  = (const float*)d_in[5];
    const float* wdec = (const float*)d_in[6];
    const float* bdec = (const float*)d_in[7];
    const float* wmom = (const float*)d_in[8];
    const float* bmom = (const float*)d_in[9];
    const float* gamma= (const float*)d_in[10];
    const float* w1   = (const float*)d_in[11];
    const float* w2   = (const float*)d_in[12];
    float* out = (float*)d_out;

    cudaFuncSetAttribute(g1_proj,  cudaFuncAttributeMaxDynamicSharedMemorySize, SMEM64);
    cudaFuncSetAttribute(g2_zgelu, cudaFuncAttributeMaxDynamicSharedMemorySize, SMEM64);
    cudaFuncSetAttribute(g3_hback, cudaFuncAttributeMaxDynamicSharedMemorySize, SMEM_3S1);
    cudaFuncSetAttribute(g4_da,    cudaFuncAttributeMaxDynamicSharedMemorySize, SMEM64);
    cudaFuncSetAttribute(g5_wp,    cudaFuncAttributeMaxDynamicSharedMemorySize, SMEM_3S2);
    cudaFuncSetAttribute(g6_z2,    cudaFuncAttributeMaxDynamicSharedMemorySize, SMEM64);
    cudaFuncSetAttribute(g7_out,   cudaFuncAttributeMaxDynamicSharedMemorySize, SMEM_3S1);

    k_half  <<<2224, 256>>>(seq, wk, wv, wq, w1, w2);
    k_dots  <<<BATCH*NC, 128>>>(seq, wlr, blr, wdec, bdec, wmom, bmom);
    k_coef  <<<1, 32>>>();
    g1_proj <<<dim3(NTOK/64, 1, 3), 256, SMEM64>>>();
    g2_zgelu<<<dim3(NTOK/64, HID/128), 256, SMEM64>>>();
    g3_hback<<<NTOK/64, NTHR, SMEM_3S1>>>(gamma);
    g4_da   <<<dim3(NTOK/64, HID/128), 256, SMEM64>>>();
    g5_wp   <<<dim3(HID/128, 2, BATCH*SLICES), NTHR, SMEM_3S2>>>();
    k_reduce<<<(BATCH*D*HID)/256, 256>>>();
    g6_z2   <<<dim3(NTOK/64, HID/128), 256, SMEM64>>>();
    g7_out  <<<NTOK/64, NTHR, SMEM_3S1>>>(out);
}